// round 12
// baseline (speedup 1.0000x reference)
#include <cuda_runtime.h>
#include <cstdint>

// ---------------------------------------------------------------------------
// GCN via one-pass bucket-CSR gather, place || gemm via graph stream fork:
//   branch A: init(zero+detect), place (bucket[dst*64+slot]=src; cur==degree)
//   branch B: p_raw = x @ W1            (independent of A)
//   join:     scale: dinv=rsqrt(1+deg); p = p_raw*dinv
//   gather1:  q[n] = dinv*(dinv*(sum p[nbr] + p[n]) + b1)
//   gather2:  h[n] = dinv*(sum q[nbr] + q[n]); pool[batch[n]] += h (red.v4)
//   headAB:   (8 blocks) z=relu((pool/cnt)@W2+b2)@fcW1+fcb1), BN partials;
//             last block: batchnorm + fc2 + softplus (all G)
// ---------------------------------------------------------------------------

#define MAXN 100000
#define MAXE 1600000
#define MAXG 256
#define C 32
#define CAP 64

__device__ int   g_bucket[MAXN * CAP];
__device__ int   g_cur[MAXN];          // placement cursor == degree afterwards
__device__ int   g_ovf_dst[MAXE];
__device__ int   g_ovf_src[MAXE];
__device__ int   g_ovf_cnt;
__device__ float g_dinv[MAXN];
__device__ float g_p[MAXN * C];
__device__ float g_q[MAXN * C];
__device__ float g_pool[MAXG * C];
__device__ float g_z[MAXG * 32];
__device__ float g_bnsum[32];
__device__ float g_bnsq[32];
__device__ int   g_head_done;
__device__ int   g_flags[2];           // [0]=edge_index int64, [1]=batch int64

static inline int ceil_div(int a, int b) { return (a + b - 1) / b; }

// Host-side stream/event objects (created once; host objects, no device mem)
struct StreamPack {
    cudaStream_t s2;
    cudaEvent_t ev_fork, ev_join;
    StreamPack() {
        cudaStreamCreateWithFlags(&s2, cudaStreamNonBlocking);
        cudaEventCreateWithFlags(&ev_fork, cudaEventDisableTiming);
        cudaEventCreateWithFlags(&ev_join, cudaEventDisableTiming);
    }
};
static StreamPack g_sp;

__device__ __forceinline__ int idx_get(const void* p, long i, int is64) {
    // int64 path: load only the low 32-bit word (values are < 2^31)
    return is64 ? ((const int*)p)[2 * i] : ((const int*)p)[i];
}

// ---------------------------------------------------------------------------
// init: zero cur/pool/bn/counters everywhere; block 0 detects index dtypes
// ---------------------------------------------------------------------------
__global__ void k_init(const unsigned* __restrict__ e, long ewords,
                       const unsigned* __restrict__ b, long bwords,
                       int N, int G) {
    int stride = gridDim.x * blockDim.x;
    int t = blockIdx.x * blockDim.x + threadIdx.x;
    for (int i = t; i < N; i += stride) g_cur[i] = 0;
    for (int i = t; i < G * C; i += stride) g_pool[i] = 0.0f;
    if (t < 32) { g_bnsum[t] = 0.0f; g_bnsq[t] = 0.0f; }
    if (t == 0) { g_ovf_cnt = 0; g_head_done = 0; }

    if (blockIdx.x == 0) {
        __shared__ unsigned se, sb;
        if (threadIdx.x == 0) { se = 0u; sb = 0u; }
        __syncthreads();
        unsigned a = 0u, c = 0u;
        long eh = ewords / 2, bh = bwords / 2;
        for (int s = 0; s < 16; s++) {
            long idx = (long)(threadIdx.x * 16 + s);
            long j = (idx * eh) / 4096;
            a |= e[2 * j + 1];
            long k = (idx * bh) / 4096;
            c |= b[2 * k + 1];
        }
        atomicOr(&se, a);
        atomicOr(&sb, c);
        __syncthreads();
        if (threadIdx.x == 0) {
            g_flags[0] = (se == 0u) ? 1 : 0;
            g_flags[1] = (sb == 0u) ? 1 : 0;
        }
    }
}

// ---------------------------------------------------------------------------
// One-pass bucket placement, 4 independent edges/thread (batched), full grid.
// ---------------------------------------------------------------------------
__global__ void k_place(const void* __restrict__ eidx, int E) {
    int is64 = g_flags[0];
    int T = gridDim.x * blockDim.x;
    int tid = blockIdx.x * blockDim.x + threadIdx.x;

    int s[4], t[4], sl[4];
    bool v[4];
#pragma unroll
    for (int u = 0; u < 4; u++) {
        int e = tid + u * T;
        v[u] = e < E;
        if (v[u]) {
            s[u] = idx_get(eidx, e, is64);
            t[u] = idx_get(eidx, (long)E + e, is64);
        }
    }
#pragma unroll
    for (int u = 0; u < 4; u++) {
        if (v[u]) sl[u] = atomicAdd(&g_cur[t[u]], 1);
    }
#pragma unroll
    for (int u = 0; u < 4; u++) {
        if (v[u]) {
            if (sl[u] < CAP) g_bucket[(size_t)t[u] * CAP + sl[u]] = s[u];
            else { int o = atomicAdd(&g_ovf_cnt, 1); g_ovf_dst[o] = t[u]; g_ovf_src[o] = s[u]; }
        }
    }
}

// ---------------------------------------------------------------------------
// GEMM raw (packed fma.rn.f32x2): p_raw[n,:] = x[n,:] @ W1  (no dinv)
// ---------------------------------------------------------------------------
__global__ void __launch_bounds__(256) k_gemm1(const float* __restrict__ x,
                                               const float* __restrict__ W1, int N) {
    __shared__ unsigned long long sW[128 * 16];
    const unsigned long long* Wp = (const unsigned long long*)W1;
    for (int i = threadIdx.x; i < 128 * 16; i += 256) sW[i] = Wp[i];
    __syncthreads();

    int n = blockIdx.x * 256 + threadIdx.x;
    if (n >= N) return;

    unsigned long long acc[16];
#pragma unroll
    for (int j = 0; j < 16; j++) acc[j] = 0ull;

    const float4* xr = (const float4*)(x + (size_t)n * 128);
#pragma unroll 2
    for (int k4 = 0; k4 < 32; k4++) {
        float4 xv = __ldg(&xr[k4]);
        const float* xf = (const float*)&xv;
#pragma unroll
        for (int kk = 0; kk < 4; kk++) {
            unsigned xb = __float_as_uint(xf[kk]);
            unsigned long long xx;
            asm("mov.b64 %0, {%1, %1};" : "=l"(xx) : "r"(xb));
            const unsigned long long* wr = sW + (k4 * 4 + kk) * 16;
#pragma unroll
            for (int j = 0; j < 16; j++) {
                asm("fma.rn.f32x2 %0, %1, %2, %0;"
                    : "+l"(acc[j]) : "l"(xx), "l"(wr[j]));
            }
        }
    }
    unsigned long long* out = (unsigned long long*)(g_p + (size_t)n * C);
#pragma unroll
    for (int j = 0; j < 16; j++) out[j] = acc[j];
}

// ---------------------------------------------------------------------------
// scale: dinv = rsqrt(1+deg); p *= dinv   (two float4 per thread, same node)
// ---------------------------------------------------------------------------
__global__ void k_scale(int N) {
    int i = blockIdx.x * 256 + threadIdx.x;   // chunk pair id
    if (i >= N * 4) return;
    int n = i >> 2;
    float di = rsqrtf(1.0f + (float)g_cur[n]);
    if ((i & 3) == 0) g_dinv[n] = di;
    float4 v0 = ((const float4*)g_p)[2 * i];
    float4 v1 = ((const float4*)g_p)[2 * i + 1];
    v0.x *= di; v0.y *= di; v0.z *= di; v0.w *= di;
    v1.x *= di; v1.y *= di; v1.z *= di; v1.w *= di;
    ((float4*)g_p)[2 * i] = v0;
    ((float4*)g_p)[2 * i + 1] = v1;
}

// ---------------------------------------------------------------------------
// Gather core: 8 threads/node, lane owns one float4 chunk; int4 index loads.
// ---------------------------------------------------------------------------
__device__ __forceinline__ float4 gather_sum(const float4* __restrict__ F,
                                             int node, int lane) {
    int deg = g_cur[node];
    int m = deg < CAP ? deg : CAP;
    const int4* bp4 = (const int4*)(g_bucket + (size_t)node * CAP);

    float4 a0 = __ldg(&F[(size_t)node * 8 + lane]);  // self-loop
    float4 a1 = make_float4(0, 0, 0, 0);
    float4 a2 = make_float4(0, 0, 0, 0);
    float4 a3 = make_float4(0, 0, 0, 0);

    int e = 0;
    for (; e + 8 <= m; e += 8) {
        int4 ia = __ldg(&bp4[e >> 2]);
        int4 ib = __ldg(&bp4[(e >> 2) + 1]);
        float4 v0 = __ldg(&F[(size_t)ia.x * 8 + lane]);
        float4 v1 = __ldg(&F[(size_t)ia.y * 8 + lane]);
        float4 v2 = __ldg(&F[(size_t)ia.z * 8 + lane]);
        float4 v3 = __ldg(&F[(size_t)ia.w * 8 + lane]);
        float4 v4 = __ldg(&F[(size_t)ib.x * 8 + lane]);
        float4 v5 = __ldg(&F[(size_t)ib.y * 8 + lane]);
        float4 v6 = __ldg(&F[(size_t)ib.z * 8 + lane]);
        float4 v7 = __ldg(&F[(size_t)ib.w * 8 + lane]);
        a0.x += v0.x; a0.y += v0.y; a0.z += v0.z; a0.w += v0.w;
        a1.x += v1.x; a1.y += v1.y; a1.z += v1.z; a1.w += v1.w;
        a2.x += v2.x; a2.y += v2.y; a2.z += v2.z; a2.w += v2.w;
        a3.x += v3.x; a3.y += v3.y; a3.z += v3.z; a3.w += v3.w;
        a0.x += v4.x; a0.y += v4.y; a0.z += v4.z; a0.w += v4.w;
        a1.x += v5.x; a1.y += v5.y; a1.z += v5.z; a1.w += v5.w;
        a2.x += v6.x; a2.y += v6.y; a2.z += v6.z; a2.w += v6.w;
        a3.x += v7.x; a3.y += v7.y; a3.z += v7.z; a3.w += v7.w;
    }
    if (e + 4 <= m) {
        int4 ia = __ldg(&bp4[e >> 2]);
        float4 v0 = __ldg(&F[(size_t)ia.x * 8 + lane]);
        float4 v1 = __ldg(&F[(size_t)ia.y * 8 + lane]);
        float4 v2 = __ldg(&F[(size_t)ia.z * 8 + lane]);
        float4 v3 = __ldg(&F[(size_t)ia.w * 8 + lane]);
        a0.x += v0.x; a0.y += v0.y; a0.z += v0.z; a0.w += v0.w;
        a1.x += v1.x; a1.y += v1.y; a1.z += v1.z; a1.w += v1.w;
        a2.x += v2.x; a2.y += v2.y; a2.z += v2.z; a2.w += v2.w;
        a3.x += v3.x; a3.y += v3.y; a3.z += v3.z; a3.w += v3.w;
        e += 4;
    }
    const int* bp = (const int*)bp4;
    for (; e < m; e++) {
        int i0 = __ldg(&bp[e]);
        float4 v0 = __ldg(&F[(size_t)i0 * 8 + lane]);
        a0.x += v0.x; a0.y += v0.y; a0.z += v0.z; a0.w += v0.w;
    }
    if (deg > CAP) {   // exact overflow handling (normally empty)
        int oc = g_ovf_cnt;
        for (int i = 0; i < oc; i++) {
            if (g_ovf_dst[i] == node) {
                float4 v = __ldg(&F[(size_t)g_ovf_src[i] * 8 + lane]);
                a0.x += v.x; a0.y += v.y; a0.z += v.z; a0.w += v.w;
            }
        }
    }
    a0.x += a1.x + a2.x + a3.x;
    a0.y += a1.y + a2.y + a3.y;
    a0.z += a1.z + a2.z + a3.z;
    a0.w += a1.w + a2.w + a3.w;
    return a0;
}

// ---------------------------------------------------------------------------
// Gather layer 1: q = dinv*(dinv*sum + b1)
// ---------------------------------------------------------------------------
__global__ void __launch_bounds__(256) k_gather1(const float* __restrict__ b1, int N) {
    int node = blockIdx.x * 32 + (threadIdx.x >> 3);
    int lane = threadIdx.x & 7;
    if (node >= N) return;

    float4 acc = gather_sum((const float4*)g_p, node, lane);

    float di = g_dinv[node];
    float4 b = ((const float4*)b1)[lane];
    float4 q;
    q.x = di * (di * acc.x + b.x);
    q.y = di * (di * acc.y + b.y);
    q.z = di * (di * acc.z + b.z);
    q.w = di * (di * acc.w + b.w);
    ((float4*)g_q)[(size_t)node * 8 + lane] = q;
}

// ---------------------------------------------------------------------------
// Gather layer 2 + fused pooling
// ---------------------------------------------------------------------------
__device__ __forceinline__ void red_add_v4(float* ptr, float4 v) {
    asm volatile("red.global.add.v4.f32 [%0], {%1, %2, %3, %4};"
                 :: "l"(ptr), "f"(v.x), "f"(v.y), "f"(v.z), "f"(v.w)
                 : "memory");
}

__global__ void __launch_bounds__(256) k_gather2(const void* __restrict__ batch, int N) {
    int node = blockIdx.x * 32 + (threadIdx.x >> 3);
    int lane = threadIdx.x & 7;
    if (node >= N) return;

    float4 acc = gather_sum((const float4*)g_q, node, lane);

    float di = g_dinv[node];
    float4 h = make_float4(di * acc.x, di * acc.y, di * acc.z, di * acc.w);
    int gidx = idx_get(batch, node, g_flags[1]);
    red_add_v4(g_pool + (size_t)gidx * C + lane * 4, h);
}

// ---------------------------------------------------------------------------
// Head (merged A+B, grid = ceil(G/32) blocks x 128 thr; 4 threads/graph):
//   z[g] = relu((pool[g]/cnt)@W2 + b2)@fcW1 + fcb1), BN partials;
//   LAST block: batchnorm + fc2 + softplus for all G.
// ---------------------------------------------------------------------------
__global__ void k_head(const void* __restrict__ batch, int N,
                       const float* __restrict__ W2, const float* __restrict__ b2,
                       const float* __restrict__ fcW1, const float* __restrict__ fcb1,
                       const float* __restrict__ gamma, const float* __restrict__ beta,
                       const float* __restrict__ fcW2, const float* __restrict__ fcb2,
                       float* __restrict__ out, int G) {
    __shared__ float sW2[32 * 64];
    __shared__ float sF1[64 * 32];
    __shared__ int s_last;
    int tid = threadIdx.x;
    for (int i = tid; i < 2048; i += 128) { sW2[i] = W2[i]; sF1[i] = fcW1[i]; }
    __syncthreads();

    int gl = tid >> 2;
    int q = tid & 3;
    int g = blockIdx.x * 32 + gl;
    int is64 = g_flags[1];

    if (g < G) {
        // node count of graph g via binary searches (duplicated across quad)
        int lo = 0, hi = N;
        while (lo < hi) { int m = (lo + hi) >> 1; if (idx_get(batch, m, is64) < g) lo = m + 1; else hi = m; }
        int start = lo;
        hi = N;
        while (lo < hi) { int m = (lo + hi) >> 1; if (idx_get(batch, m, is64) < g + 1) lo = m + 1; else hi = m; }
        int cnt = lo - start;
        float inv_cnt = 1.0f / (float)max(cnt, 1);

        float r[32];
#pragma unroll
        for (int i = 0; i < 32; i++) r[i] = __ldg(&g_pool[g * 32 + i]) * inv_cnt;

        // o2 slice [q*16, q*16+16)
        float o2[16];
#pragma unroll
        for (int j = 0; j < 16; j++) o2[j] = __ldg(&b2[q * 16 + j]);
        for (int k = 0; k < 32; k++) {
            float rk = r[k];
            const float* wrow = sW2 + k * 64 + q * 16;
#pragma unroll
            for (int j = 0; j < 16; j++) o2[j] = fmaf(rk, wrow[j], o2[j]);
        }

        // z partial from this slice
        float zz[32];
#pragma unroll
        for (int i = 0; i < 32; i++) zz[i] = 0.0f;
        for (int j = 0; j < 16; j++) {
            float oj = o2[j];
            const float* frow = sF1 + (q * 16 + j) * 32;
#pragma unroll
            for (int i = 0; i < 32; i++) zz[i] = fmaf(oj, frow[i], zz[i]);
        }

        // combine quad partials (lanes 4k..4k+3 hold the same graph)
        unsigned fm = 0xFFFFFFFFu;
#pragma unroll
        for (int i = 0; i < 32; i++) {
            zz[i] += __shfl_xor_sync(fm, zz[i], 1);
            zz[i] += __shfl_xor_sync(fm, zz[i], 2);
        }

        // z = relu(sum + fcb1); store (q==0) and accumulate BN partials
        float z[32];
#pragma unroll
        for (int i = 0; i < 32; i++) z[i] = fmaxf(zz[i] + __ldg(&fcb1[i]), 0.0f);
        if (q == 0) {
#pragma unroll
            for (int i = 0; i < 32; i++) g_z[g * 32 + i] = z[i];
        }
        for (int i = 0; i < 32; i++) {
            float v = (q == 0) ? z[i] : 0.0f;
            float v2 = v * v;
#pragma unroll
            for (int o = 16; o > 0; o >>= 1) {
                v += __shfl_down_sync(fm, v, o);
                v2 += __shfl_down_sync(fm, v2, o);
            }
            if ((tid & 31) == 0) {
                atomicAdd(&g_bnsum[i], v);
                atomicAdd(&g_bnsq[i], v2);
            }
        }
    }

    // last-block takes over phase B
    __syncthreads();
    __threadfence();
    if (tid == 0) {
        int prev = atomicAdd(&g_head_done, 1);
        s_last = (prev == (int)gridDim.x - 1) ? 1 : 0;
    }
    __syncthreads();
    if (!s_last) return;

    __shared__ float smu[32], sis[32], sgam[32], sbet[32], sfw2[32];
    if (tid < 32) {
        float invG = 1.0f / (float)G;
        float mu = g_bnsum[tid] * invG;
        float var = g_bnsq[tid] * invG - mu * mu;
        smu[tid] = mu;
        sis[tid] = rsqrtf(var + 1e-5f);
        sgam[tid] = gamma[tid];
        sbet[tid] = beta[tid];
        sfw2[tid] = fcW2[tid];
    }
    __syncthreads();

    float fb2 = __ldg(&fcb2[0]);
    for (int gg = tid; gg < G; gg += blockDim.x) {
        float acc = fb2;
#pragma unroll
        for (int i = 0; i < 32; i++) {
            float zb = (g_z[gg * 32 + i] - smu[i]) * sis[i] * sgam[i] + sbet[i];
            acc = fmaf(zb, sfw2[i], acc);
        }
        out[gg] = fmaxf(acc, 0.0f) + log1pf(expf(-fabsf(acc)));
    }
}

// ---------------------------------------------------------------------------
extern "C" void kernel_launch(void* const* d_in, const int* in_sizes, int n_in,
                              void* d_out, int out_size) {
    const float* x     = (const float*)d_in[0];
    const void*  eidx  = d_in[1];
    const void*  batch = d_in[2];
    const float* W1    = (const float*)d_in[3];
    const float* b1    = (const float*)d_in[4];
    const float* W2    = (const float*)d_in[5];
    const float* b2    = (const float*)d_in[6];
    const float* fcW1  = (const float*)d_in[7];
    const float* fcb1  = (const float*)d_in[8];
    const float* gamma = (const float*)d_in[9];
    const float* beta  = (const float*)d_in[10];
    const float* fcW2  = (const float*)d_in[11];
    const float* fcb2  = (const float*)d_in[12];

    int N = in_sizes[0] / 128;
    int E = in_sizes[1] / 2;
    int G = out_size;

    // Fork: branch B (s2) runs the GEMM, independent of the CSR build.
    cudaEventRecord(g_sp.ev_fork, 0);
    cudaStreamWaitEvent(g_sp.s2, g_sp.ev_fork, 0);
    k_gemm1<<<ceil_div(N, 256), 256, 0, g_sp.s2>>>(x, W1, N);
    cudaEventRecord(g_sp.ev_join, g_sp.s2);

    // Branch A: init(zero+detect) + place on the default stream.
    k_init<<<128, 256>>>((const unsigned*)eidx, (long)2 * E,
                         (const unsigned*)batch, (long)N, N, G);
    k_place<<<ceil_div(E, 1024), 256>>>(eidx, E);

    // Join and finish serial tail.
    cudaStreamWaitEvent(0, g_sp.ev_join, 0);
    k_scale<<<ceil_div(N * 4, 256), 256>>>(N);
    k_gather1<<<ceil_div(N, 32), 256>>>(b1, N);
    k_gather2<<<ceil_div(N, 32), 256>>>(batch, N);
    k_head<<<ceil_div(G, 32), 128>>>(batch, N, W2, b2, fcW1, fcb1,
                                     gamma, beta, fcW2, fcb2,
                                     (float*)d_out, G);
}

// round 13
// speedup vs baseline: 1.0025x; 1.0025x over previous
#include <cuda_runtime.h>
#include <cstdint>

// ---------------------------------------------------------------------------
// GCN via one-pass bucket-CSR gather, place || gemm via graph stream fork:
//   branch A: memsets, detect, place (bucket[dst*64+slot]=src; cur==degree)
//   branch B: p_raw = x @ W1            (independent of A)
//   join:     scale: dinv=rsqrt(1+deg); p = p_raw*dinv
//   gather1:  q[n] = dinv*(dinv*(sum p[nbr] + p[n]) + b1)   [sw-pipelined]
//   gather2:  h[n] = dinv*(sum q[nbr] + q[n]); pool[batch[n]] += h (red.v4)
//   headA:    (8 blocks) z = relu((pool/cnt)@W2+b2)@fcW1+fcb1), BN partials
//   headB:    (1 block)  batchnorm + fc2 + softplus
// ---------------------------------------------------------------------------

#define MAXN 100000
#define MAXE 1600000
#define MAXG 256
#define C 32
#define CAP 64

__device__ int   g_bucket[MAXN * CAP];
__device__ int   g_cur[MAXN];          // placement cursor == degree afterwards
__device__ int   g_ovf_dst[MAXE];
__device__ int   g_ovf_src[MAXE];
__device__ int   g_ovf_cnt;
__device__ float g_dinv[MAXN];
__device__ float g_p[MAXN * C];
__device__ float g_q[MAXN * C];
__device__ float g_pool[MAXG * C];
__device__ float g_z[MAXG * 32];
__device__ float g_bnsum[32];
__device__ float g_bnsq[32];
__device__ int   g_flags[2];           // [0]=edge_index int64, [1]=batch int64

static inline int ceil_div(int a, int b) { return (a + b - 1) / b; }

// Host-side stream/event objects (created once; host objects, no device mem)
struct StreamPack {
    cudaStream_t s2;
    cudaEvent_t ev_fork, ev_join;
    StreamPack() {
        cudaStreamCreateWithFlags(&s2, cudaStreamNonBlocking);
        cudaEventCreateWithFlags(&ev_fork, cudaEventDisableTiming);
        cudaEventCreateWithFlags(&ev_join, cudaEventDisableTiming);
    }
};
static StreamPack g_sp;

__device__ __forceinline__ int idx_get(const void* p, long i, int is64) {
    // int64 path: load only the low 32-bit word (values are < 2^31)
    return is64 ? ((const int*)p)[2 * i] : ((const int*)p)[i];
}

// ---------------------------------------------------------------------------
// dtype detect + small scalar zero-inits
// ---------------------------------------------------------------------------
__global__ void k_detect(const unsigned* __restrict__ e, long ewords,
                         const unsigned* __restrict__ b, long bwords) {
    __shared__ unsigned se, sb;
    if (threadIdx.x == 0) { se = 0u; sb = 0u; g_ovf_cnt = 0; }
    if (threadIdx.x < 32) { g_bnsum[threadIdx.x] = 0.0f; g_bnsq[threadIdx.x] = 0.0f; }
    __syncthreads();
    unsigned a = 0u, c = 0u;
    long eh = ewords / 2, bh = bwords / 2;
    for (int s = 0; s < 16; s++) {
        long idx = (long)(threadIdx.x * 16 + s);
        long j = (idx * eh) / 4096;
        a |= e[2 * j + 1];
        long k = (idx * bh) / 4096;
        c |= b[2 * k + 1];
    }
    atomicOr(&se, a);
    atomicOr(&sb, c);
    __syncthreads();
    if (threadIdx.x == 0) {
        g_flags[0] = (se == 0u) ? 1 : 0;
        g_flags[1] = (sb == 0u) ? 1 : 0;
    }
}

// ---------------------------------------------------------------------------
// One-pass bucket placement, 4 independent edges/thread (batched), full grid.
// ---------------------------------------------------------------------------
__global__ void k_place(const void* __restrict__ eidx, int E) {
    int is64 = g_flags[0];
    int T = gridDim.x * blockDim.x;
    int tid = blockIdx.x * blockDim.x + threadIdx.x;

    int s[4], t[4], sl[4];
    bool v[4];
#pragma unroll
    for (int u = 0; u < 4; u++) {
        int e = tid + u * T;
        v[u] = e < E;
        if (v[u]) {
            s[u] = idx_get(eidx, e, is64);
            t[u] = idx_get(eidx, (long)E + e, is64);
        }
    }
#pragma unroll
    for (int u = 0; u < 4; u++) {
        if (v[u]) sl[u] = atomicAdd(&g_cur[t[u]], 1);
    }
#pragma unroll
    for (int u = 0; u < 4; u++) {
        if (v[u]) {
            if (sl[u] < CAP) g_bucket[(size_t)t[u] * CAP + sl[u]] = s[u];
            else { int o = atomicAdd(&g_ovf_cnt, 1); g_ovf_dst[o] = t[u]; g_ovf_src[o] = s[u]; }
        }
    }
}

// ---------------------------------------------------------------------------
// GEMM raw (packed fma.rn.f32x2): p_raw[n,:] = x[n,:] @ W1  (no dinv)
// ---------------------------------------------------------------------------
__global__ void __launch_bounds__(256) k_gemm1(const float* __restrict__ x,
                                               const float* __restrict__ W1, int N) {
    __shared__ unsigned long long sW[128 * 16];
    const unsigned long long* Wp = (const unsigned long long*)W1;
    for (int i = threadIdx.x; i < 128 * 16; i += 256) sW[i] = Wp[i];
    __syncthreads();

    int n = blockIdx.x * 256 + threadIdx.x;
    if (n >= N) return;

    unsigned long long acc[16];
#pragma unroll
    for (int j = 0; j < 16; j++) acc[j] = 0ull;

    const float4* xr = (const float4*)(x + (size_t)n * 128);
#pragma unroll 2
    for (int k4 = 0; k4 < 32; k4++) {
        float4 xv = __ldg(&xr[k4]);
        const float* xf = (const float*)&xv;
#pragma unroll
        for (int kk = 0; kk < 4; kk++) {
            unsigned xb = __float_as_uint(xf[kk]);
            unsigned long long xx;
            asm("mov.b64 %0, {%1, %1};" : "=l"(xx) : "r"(xb));
            const unsigned long long* wr = sW + (k4 * 4 + kk) * 16;
#pragma unroll
            for (int j = 0; j < 16; j++) {
                asm("fma.rn.f32x2 %0, %1, %2, %0;"
                    : "+l"(acc[j]) : "l"(xx), "l"(wr[j]));
            }
        }
    }
    unsigned long long* out = (unsigned long long*)(g_p + (size_t)n * C);
#pragma unroll
    for (int j = 0; j < 16; j++) out[j] = acc[j];
}

// ---------------------------------------------------------------------------
// scale: dinv = rsqrt(1+deg); p *= dinv   (two float4 per thread, same node)
// ---------------------------------------------------------------------------
__global__ void k_scale(int N) {
    int i = blockIdx.x * 256 + threadIdx.x;   // chunk pair id
    if (i >= N * 4) return;
    int n = i >> 2;
    float di = rsqrtf(1.0f + (float)g_cur[n]);
    if ((i & 3) == 0) g_dinv[n] = di;
    float4 v0 = ((const float4*)g_p)[2 * i];
    float4 v1 = ((const float4*)g_p)[2 * i + 1];
    v0.x *= di; v0.y *= di; v0.z *= di; v0.w *= di;
    v1.x *= di; v1.y *= di; v1.z *= di; v1.w *= di;
    ((float4*)g_p)[2 * i] = v0;
    ((float4*)g_p)[2 * i + 1] = v1;
}

// ---------------------------------------------------------------------------
// Gather core: 8 threads/node, lane owns one float4 chunk.
// Software-pipelined: next iteration's index vectors (int4 pair) are issued
// BEFORE the current iteration's feature loads are consumed, so the
// idx->feature dependency chain overlaps across iterations.
// ---------------------------------------------------------------------------
__device__ __forceinline__ float4 gather_sum(const float4* __restrict__ F,
                                             int node, int lane) {
    int deg = g_cur[node];
    int m = deg < CAP ? deg : CAP;
    const int4* bp4 = (const int4*)(g_bucket + (size_t)node * CAP);

    float4 a0 = __ldg(&F[(size_t)node * 8 + lane]);  // self-loop
    float4 a1 = make_float4(0, 0, 0, 0);
    float4 a2 = make_float4(0, 0, 0, 0);
    float4 a3 = make_float4(0, 0, 0, 0);

    int e = 0;
    if (e + 8 <= m) {
        // prologue: first index pair
        int4 ia = __ldg(&bp4[0]);
        int4 ib = __ldg(&bp4[1]);
        for (; e + 8 <= m; ) {
            // prefetch next indices before touching current features
            int4 na, nb;
            bool more = (e + 16 <= m);
            if (more) {
                na = __ldg(&bp4[(e >> 2) + 2]);
                nb = __ldg(&bp4[(e >> 2) + 3]);
            }
            float4 v0 = __ldg(&F[(size_t)ia.x * 8 + lane]);
            float4 v1 = __ldg(&F[(size_t)ia.y * 8 + lane]);
            float4 v2 = __ldg(&F[(size_t)ia.z * 8 + lane]);
            float4 v3 = __ldg(&F[(size_t)ia.w * 8 + lane]);
            float4 v4 = __ldg(&F[(size_t)ib.x * 8 + lane]);
            float4 v5 = __ldg(&F[(size_t)ib.y * 8 + lane]);
            float4 v6 = __ldg(&F[(size_t)ib.z * 8 + lane]);
            float4 v7 = __ldg(&F[(size_t)ib.w * 8 + lane]);
            a0.x += v0.x; a0.y += v0.y; a0.z += v0.z; a0.w += v0.w;
            a1.x += v1.x; a1.y += v1.y; a1.z += v1.z; a1.w += v1.w;
            a2.x += v2.x; a2.y += v2.y; a2.z += v2.z; a2.w += v2.w;
            a3.x += v3.x; a3.y += v3.y; a3.z += v3.z; a3.w += v3.w;
            a0.x += v4.x; a0.y += v4.y; a0.z += v4.z; a0.w += v4.w;
            a1.x += v5.x; a1.y += v5.y; a1.z += v5.z; a1.w += v5.w;
            a2.x += v6.x; a2.y += v6.y; a2.z += v6.z; a2.w += v6.w;
            a3.x += v7.x; a3.y += v7.y; a3.z += v7.z; a3.w += v7.w;
            e += 8;
            ia = na; ib = nb;
        }
    }
    if (e + 4 <= m) {
        int4 ia = __ldg(&bp4[e >> 2]);
        float4 v0 = __ldg(&F[(size_t)ia.x * 8 + lane]);
        float4 v1 = __ldg(&F[(size_t)ia.y * 8 + lane]);
        float4 v2 = __ldg(&F[(size_t)ia.z * 8 + lane]);
        float4 v3 = __ldg(&F[(size_t)ia.w * 8 + lane]);
        a0.x += v0.x; a0.y += v0.y; a0.z += v0.z; a0.w += v0.w;
        a1.x += v1.x; a1.y += v1.y; a1.z += v1.z; a1.w += v1.w;
        a2.x += v2.x; a2.y += v2.y; a2.z += v2.z; a2.w += v2.w;
        a3.x += v3.x; a3.y += v3.y; a3.z += v3.z; a3.w += v3.w;
        e += 4;
    }
    const int* bp = (const int*)bp4;
    for (; e < m; e++) {
        int i0 = __ldg(&bp[e]);
        float4 v0 = __ldg(&F[(size_t)i0 * 8 + lane]);
        a0.x += v0.x; a0.y += v0.y; a0.z += v0.z; a0.w += v0.w;
    }
    if (deg > CAP) {   // exact overflow handling (normally empty)
        int oc = g_ovf_cnt;
        for (int i = 0; i < oc; i++) {
            if (g_ovf_dst[i] == node) {
                float4 v = __ldg(&F[(size_t)g_ovf_src[i] * 8 + lane]);
                a0.x += v.x; a0.y += v.y; a0.z += v.z; a0.w += v.w;
            }
        }
    }
    a0.x += a1.x + a2.x + a3.x;
    a0.y += a1.y + a2.y + a3.y;
    a0.z += a1.z + a2.z + a3.z;
    a0.w += a1.w + a2.w + a3.w;
    return a0;
}

// ---------------------------------------------------------------------------
// Gather layer 1: q = dinv*(dinv*sum + b1)
// ---------------------------------------------------------------------------
__global__ void __launch_bounds__(256) k_gather1(const float* __restrict__ b1, int N) {
    int node = blockIdx.x * 32 + (threadIdx.x >> 3);
    int lane = threadIdx.x & 7;
    if (node >= N) return;

    float4 acc = gather_sum((const float4*)g_p, node, lane);

    float di = g_dinv[node];
    float4 b = ((const float4*)b1)[lane];
    float4 q;
    q.x = di * (di * acc.x + b.x);
    q.y = di * (di * acc.y + b.y);
    q.z = di * (di * acc.z + b.z);
    q.w = di * (di * acc.w + b.w);
    ((float4*)g_q)[(size_t)node * 8 + lane] = q;
}

// ---------------------------------------------------------------------------
// Gather layer 2 + fused pooling
// ---------------------------------------------------------------------------
__device__ __forceinline__ void red_add_v4(float* ptr, float4 v) {
    asm volatile("red.global.add.v4.f32 [%0], {%1, %2, %3, %4};"
                 :: "l"(ptr), "f"(v.x), "f"(v.y), "f"(v.z), "f"(v.w)
                 : "memory");
}

__global__ void __launch_bounds__(256) k_gather2(const void* __restrict__ batch, int N) {
    int node = blockIdx.x * 32 + (threadIdx.x >> 3);
    int lane = threadIdx.x & 7;
    if (node >= N) return;

    float4 acc = gather_sum((const float4*)g_q, node, lane);

    float di = g_dinv[node];
    float4 h = make_float4(di * acc.x, di * acc.y, di * acc.z, di * acc.w);
    int gidx = idx_get(batch, node, g_flags[1]);
    red_add_v4(g_pool + (size_t)gidx * C + lane * 4, h);
}

// ---------------------------------------------------------------------------
// Head phase A (grid = ceil(G/32) blocks x 128 thr; 4 threads per graph):
//   z[g] = relu((pool[g]/cnt)@W2 + b2)@fcW1 + fcb1), BN partial sums.
// ---------------------------------------------------------------------------
__global__ void k_headA(const void* __restrict__ batch, int N,
                        const float* __restrict__ W2, const float* __restrict__ b2,
                        const float* __restrict__ fcW1, const float* __restrict__ fcb1,
                        int G) {
    __shared__ float sW2[32 * 64];
    __shared__ float sF1[64 * 32];
    int tid = threadIdx.x;
    for (int i = tid; i < 2048; i += 128) { sW2[i] = W2[i]; sF1[i] = fcW1[i]; }
    __syncthreads();

    int gl = tid >> 2;
    int q = tid & 3;
    int g = blockIdx.x * 32 + gl;
    if (g >= G) return;
    int is64 = g_flags[1];

    int lo = 0, hi = N;
    while (lo < hi) { int m = (lo + hi) >> 1; if (idx_get(batch, m, is64) < g) lo = m + 1; else hi = m; }
    int start = lo;
    hi = N;
    while (lo < hi) { int m = (lo + hi) >> 1; if (idx_get(batch, m, is64) < g + 1) lo = m + 1; else hi = m; }
    int cnt = lo - start;
    float inv_cnt = 1.0f / (float)max(cnt, 1);

    float r[32];
#pragma unroll
    for (int i = 0; i < 32; i++) r[i] = __ldg(&g_pool[g * 32 + i]) * inv_cnt;

    float o2[16];
#pragma unroll
    for (int j = 0; j < 16; j++) o2[j] = __ldg(&b2[q * 16 + j]);
    for (int k = 0; k < 32; k++) {
        float rk = r[k];
        const float* wrow = sW2 + k * 64 + q * 16;
#pragma unroll
        for (int j = 0; j < 16; j++) o2[j] = fmaf(rk, wrow[j], o2[j]);
    }

    float zz[32];
#pragma unroll
    for (int i = 0; i < 32; i++) zz[i] = 0.0f;
    for (int j = 0; j < 16; j++) {
        float oj = o2[j];
        const float* frow = sF1 + (q * 16 + j) * 32;
#pragma unroll
        for (int i = 0; i < 32; i++) zz[i] = fmaf(oj, frow[i], zz[i]);
    }

    unsigned fm = 0xFFFFFFFFu;
#pragma unroll
    for (int i = 0; i < 32; i++) {
        zz[i] += __shfl_xor_sync(fm, zz[i], 1);
        zz[i] += __shfl_xor_sync(fm, zz[i], 2);
    }

    float z[32];
#pragma unroll
    for (int i = 0; i < 32; i++) z[i] = fmaxf(zz[i] + __ldg(&fcb1[i]), 0.0f);
    if (q == 0) {
#pragma unroll
        for (int i = 0; i < 32; i++) g_z[g * 32 + i] = z[i];
    }
    for (int i = 0; i < 32; i++) {
        float v = (q == 0) ? z[i] : 0.0f;
        float v2 = v * v;
#pragma unroll
        for (int o = 16; o > 0; o >>= 1) {
            v += __shfl_down_sync(fm, v, o);
            v2 += __shfl_down_sync(fm, v2, o);
        }
        if ((tid & 31) == 0) {
            atomicAdd(&g_bnsum[i], v);
            atomicAdd(&g_bnsq[i], v2);
        }
    }
}

// ---------------------------------------------------------------------------
// Head phase B (1 block, 1 thread/graph): batchnorm + fc2 + softplus
// ---------------------------------------------------------------------------
__global__ void k_headB(const float* __restrict__ gamma, const float* __restrict__ beta,
                        const float* __restrict__ fcW2, const float* __restrict__ fcb2,
                        float* __restrict__ out, int G) {
    __shared__ float smu[32], sis[32], sgam[32], sbet[32], sfw2[32];
    int tid = threadIdx.x;
    if (tid < 32) {
        float invG = 1.0f / (float)G;
        float mu = g_bnsum[tid] * invG;
        float var = g_bnsq[tid] * invG - mu * mu;
        smu[tid] = mu;
        sis[tid] = rsqrtf(var + 1e-5f);
        sgam[tid] = gamma[tid];
        sbet[tid] = beta[tid];
        sfw2[tid] = fcW2[tid];
    }
    __syncthreads();
    if (tid >= G) return;

    float acc = __ldg(&fcb2[0]);
#pragma unroll
    for (int i = 0; i < 32; i++) {
        float zb = (g_z[tid * 32 + i] - smu[i]) * sis[i] * sgam[i] + sbet[i];
        acc = fmaf(zb, sfw2[i], acc);
    }
    out[tid] = fmaxf(acc, 0.0f) + log1pf(expf(-fabsf(acc)));
}

// ---------------------------------------------------------------------------
extern "C" void kernel_launch(void* const* d_in, const int* in_sizes, int n_in,
                              void* d_out, int out_size) {
    const float* x     = (const float*)d_in[0];
    const void*  eidx  = d_in[1];
    const void*  batch = d_in[2];
    const float* W1    = (const float*)d_in[3];
    const float* b1    = (const float*)d_in[4];
    const float* W2    = (const float*)d_in[5];
    const float* b2    = (const float*)d_in[6];
    const float* fcW1  = (const float*)d_in[7];
    const float* fcb1  = (const float*)d_in[8];
    const float* gamma = (const float*)d_in[9];
    const float* beta  = (const float*)d_in[10];
    const float* fcW2  = (const float*)d_in[11];
    const float* fcb2  = (const float*)d_in[12];

    int N = in_sizes[0] / 128;
    int E = in_sizes[1] / 2;
    int G = out_size;

    void *pcur, *ppool;
    cudaGetSymbolAddress(&pcur, g_cur);
    cudaGetSymbolAddress(&ppool, g_pool);

    // Fork: branch B (s2) runs the GEMM, independent of the CSR build.
    cudaEventRecord(g_sp.ev_fork, 0);
    cudaStreamWaitEvent(g_sp.s2, g_sp.ev_fork, 0);
    k_gemm1<<<ceil_div(N, 256), 256, 0, g_sp.s2>>>(x, W1, N);
    cudaEventRecord(g_sp.ev_join, g_sp.s2);

    // Branch A: init + detect + place on the default stream.
    cudaMemsetAsync(pcur, 0, (size_t)N * sizeof(int));
    cudaMemsetAsync(ppool, 0, (size_t)G * C * sizeof(float));
    k_detect<<<1, 256>>>((const unsigned*)eidx, (long)2 * E,
                         (const unsigned*)batch, (long)N);
    k_place<<<ceil_div(E, 1024), 256>>>(eidx, E);

    // Join and finish serial tail.
    cudaStreamWaitEvent(0, g_sp.ev_join, 0);
    k_scale<<<ceil_div(N * 4, 256), 256>>>(N);
    k_gather1<<<ceil_div(N, 32), 256>>>(b1, N);
    k_gather2<<<ceil_div(N, 32), 256>>>(batch, N);
    k_headA<<<ceil_div(G, 32), 128>>>(batch, N, W2, b2, fcW1, fcb1, G);
    k_headB<<<1, G>>>(gamma, beta, fcW2, fcb2, (float*)d_out, G);
}

// round 14
// speedup vs baseline: 1.0565x; 1.0539x over previous
#include <cuda_runtime.h>
#include <cuda_fp16.h>
#include <cstdint>

// ---------------------------------------------------------------------------
// GCN via one-pass bucket-CSR gather, place || gemm via graph stream fork.
// Inter-layer features stored as fp16 (halves gather bandwidth); all
// accumulation in fp32.
//   branch A: memsets, detect, place (bucket[dst*64+slot]=src; cur==degree)
//   branch B: p_raw = x @ W1 (fp32)
//   join:     scale: dinv=rsqrt(1+deg); ph = half(p_raw*dinv)
//   gather1:  q[n] = dinv*(dinv*(sum ph[nbr] + ph[n]) + b1)  -> qh (half)
//   gather2:  h[n] = dinv*(sum qh[nbr] + qh[n]); pool[batch[n]] += h (red.v4)
//   headA:    (8 blocks) z = relu((pool/cnt)@W2+b2)@fcW1+fcb1), BN partials
//   headB:    (1 block)  batchnorm + fc2 + softplus
// ---------------------------------------------------------------------------

#define MAXN 100000
#define MAXE 1600000
#define MAXG 256
#define C 32
#define CAP 64

__device__ int    g_bucket[MAXN * CAP];
__device__ int    g_cur[MAXN];         // placement cursor == degree afterwards
__device__ int    g_ovf_dst[MAXE];
__device__ int    g_ovf_src[MAXE];
__device__ int    g_ovf_cnt;
__device__ float  g_dinv[MAXN];
__device__ float  g_p[MAXN * C];       // fp32 p_raw from GEMM
__device__ __half g_ph[MAXN * C];      // half p (scaled), gather-1 source
__device__ __half g_qh[MAXN * C];      // half q, gather-2 source
__device__ float  g_pool[MAXG * C];
__device__ float  g_z[MAXG * 32];
__device__ float  g_bnsum[32];
__device__ float  g_bnsq[32];
__device__ int    g_flags[2];          // [0]=edge_index int64, [1]=batch int64

static inline int ceil_div(int a, int b) { return (a + b - 1) / b; }

// Host-side stream/event objects (created once; host objects, no device mem)
struct StreamPack {
    cudaStream_t s2;
    cudaEvent_t ev_fork, ev_join;
    StreamPack() {
        cudaStreamCreateWithFlags(&s2, cudaStreamNonBlocking);
        cudaEventCreateWithFlags(&ev_fork, cudaEventDisableTiming);
        cudaEventCreateWithFlags(&ev_join, cudaEventDisableTiming);
    }
};
static StreamPack g_sp;

__device__ __forceinline__ int idx_get(const void* p, long i, int is64) {
    // int64 path: load only the low 32-bit word (values are < 2^31)
    return is64 ? ((const int*)p)[2 * i] : ((const int*)p)[i];
}

// ---------------------------------------------------------------------------
// dtype detect + small scalar zero-inits
// ---------------------------------------------------------------------------
__global__ void k_detect(const unsigned* __restrict__ e, long ewords,
                         const unsigned* __restrict__ b, long bwords) {
    __shared__ unsigned se, sb;
    if (threadIdx.x == 0) { se = 0u; sb = 0u; g_ovf_cnt = 0; }
    if (threadIdx.x < 32) { g_bnsum[threadIdx.x] = 0.0f; g_bnsq[threadIdx.x] = 0.0f; }
    __syncthreads();
    unsigned a = 0u, c = 0u;
    long eh = ewords / 2, bh = bwords / 2;
    for (int s = 0; s < 16; s++) {
        long idx = (long)(threadIdx.x * 16 + s);
        long j = (idx * eh) / 4096;
        a |= e[2 * j + 1];
        long k = (idx * bh) / 4096;
        c |= b[2 * k + 1];
    }
    atomicOr(&se, a);
    atomicOr(&sb, c);
    __syncthreads();
    if (threadIdx.x == 0) {
        g_flags[0] = (se == 0u) ? 1 : 0;
        g_flags[1] = (sb == 0u) ? 1 : 0;
    }
}

// ---------------------------------------------------------------------------
// One-pass bucket placement, 4 independent edges/thread (batched), full grid.
// ---------------------------------------------------------------------------
__global__ void k_place(const void* __restrict__ eidx, int E) {
    int is64 = g_flags[0];
    int T = gridDim.x * blockDim.x;
    int tid = blockIdx.x * blockDim.x + threadIdx.x;

    int s[4], t[4], sl[4];
    bool v[4];
#pragma unroll
    for (int u = 0; u < 4; u++) {
        int e = tid + u * T;
        v[u] = e < E;
        if (v[u]) {
            s[u] = idx_get(eidx, e, is64);
            t[u] = idx_get(eidx, (long)E + e, is64);
        }
    }
#pragma unroll
    for (int u = 0; u < 4; u++) {
        if (v[u]) sl[u] = atomicAdd(&g_cur[t[u]], 1);
    }
#pragma unroll
    for (int u = 0; u < 4; u++) {
        if (v[u]) {
            if (sl[u] < CAP) g_bucket[(size_t)t[u] * CAP + sl[u]] = s[u];
            else { int o = atomicAdd(&g_ovf_cnt, 1); g_ovf_dst[o] = t[u]; g_ovf_src[o] = s[u]; }
        }
    }
}

// ---------------------------------------------------------------------------
// GEMM raw (packed fma.rn.f32x2): p_raw[n,:] = x[n,:] @ W1  (fp32, no dinv)
// ---------------------------------------------------------------------------
__global__ void __launch_bounds__(256) k_gemm1(const float* __restrict__ x,
                                               const float* __restrict__ W1, int N) {
    __shared__ unsigned long long sW[128 * 16];
    const unsigned long long* Wp = (const unsigned long long*)W1;
    for (int i = threadIdx.x; i < 128 * 16; i += 256) sW[i] = Wp[i];
    __syncthreads();

    int n = blockIdx.x * 256 + threadIdx.x;
    if (n >= N) return;

    unsigned long long acc[16];
#pragma unroll
    for (int j = 0; j < 16; j++) acc[j] = 0ull;

    const float4* xr = (const float4*)(x + (size_t)n * 128);
#pragma unroll 2
    for (int k4 = 0; k4 < 32; k4++) {
        float4 xv = __ldg(&xr[k4]);
        const float* xf = (const float*)&xv;
#pragma unroll
        for (int kk = 0; kk < 4; kk++) {
            unsigned xb = __float_as_uint(xf[kk]);
            unsigned long long xx;
            asm("mov.b64 %0, {%1, %1};" : "=l"(xx) : "r"(xb));
            const unsigned long long* wr = sW + (k4 * 4 + kk) * 16;
#pragma unroll
            for (int j = 0; j < 16; j++) {
                asm("fma.rn.f32x2 %0, %1, %2, %0;"
                    : "+l"(acc[j]) : "l"(xx), "l"(wr[j]));
            }
        }
    }
    unsigned long long* out = (unsigned long long*)(g_p + (size_t)n * C);
#pragma unroll
    for (int j = 0; j < 16; j++) out[j] = acc[j];
}

// ---------------------------------------------------------------------------
// scale: dinv = rsqrt(1+deg); ph = half(p_raw * dinv)
// one thread = 8 floats in -> 8 halves out (uint4 store)
// ---------------------------------------------------------------------------
__global__ void k_scale(int N) {
    int i = blockIdx.x * 256 + threadIdx.x;   // 8-element chunk id
    if (i >= N * 4) return;
    int n = i >> 2;
    float di = rsqrtf(1.0f + (float)g_cur[n]);
    if ((i & 3) == 0) g_dinv[n] = di;
    float4 v0 = ((const float4*)g_p)[2 * i];
    float4 v1 = ((const float4*)g_p)[2 * i + 1];
    __half2 h0 = __floats2half2_rn(v0.x * di, v0.y * di);
    __half2 h1 = __floats2half2_rn(v0.z * di, v0.w * di);
    __half2 h2 = __floats2half2_rn(v1.x * di, v1.y * di);
    __half2 h3 = __floats2half2_rn(v1.z * di, v1.w * di);
    uint4 st;
    st.x = *(unsigned*)&h0; st.y = *(unsigned*)&h1;
    st.z = *(unsigned*)&h2; st.w = *(unsigned*)&h3;
    ((uint4*)g_ph)[i] = st;
}

// ---------------------------------------------------------------------------
// Gather core (half source): 8 threads/node, lane owns 4 halves (8B LDG).
// Accumulation in fp32. int4 index loads; 8-edge unroll, 4 accumulators.
// ---------------------------------------------------------------------------
__device__ __forceinline__ void acc_h4(uint2 v, float4& a) {
    __half2 h0 = *reinterpret_cast<__half2*>(&v.x);
    __half2 h1 = *reinterpret_cast<__half2*>(&v.y);
    float2 f0 = __half22float2(h0);
    float2 f1 = __half22float2(h1);
    a.x += f0.x; a.y += f0.y; a.z += f1.x; a.w += f1.y;
}

__device__ __forceinline__ float4 gather_sum_h(const uint2* __restrict__ F,
                                               int node, int lane) {
    int deg = g_cur[node];
    int m = deg < CAP ? deg : CAP;
    const int4* bp4 = (const int4*)(g_bucket + (size_t)node * CAP);

    float4 a0 = make_float4(0, 0, 0, 0);
    float4 a1 = make_float4(0, 0, 0, 0);
    float4 a2 = make_float4(0, 0, 0, 0);
    float4 a3 = make_float4(0, 0, 0, 0);
    acc_h4(__ldg(&F[(size_t)node * 8 + lane]), a0);  // self-loop

    int e = 0;
    for (; e + 8 <= m; e += 8) {
        int4 ia = __ldg(&bp4[e >> 2]);
        int4 ib = __ldg(&bp4[(e >> 2) + 1]);
        uint2 v0 = __ldg(&F[(size_t)ia.x * 8 + lane]);
        uint2 v1 = __ldg(&F[(size_t)ia.y * 8 + lane]);
        uint2 v2 = __ldg(&F[(size_t)ia.z * 8 + lane]);
        uint2 v3 = __ldg(&F[(size_t)ia.w * 8 + lane]);
        uint2 v4 = __ldg(&F[(size_t)ib.x * 8 + lane]);
        uint2 v5 = __ldg(&F[(size_t)ib.y * 8 + lane]);
        uint2 v6 = __ldg(&F[(size_t)ib.z * 8 + lane]);
        uint2 v7 = __ldg(&F[(size_t)ib.w * 8 + lane]);
        acc_h4(v0, a0); acc_h4(v1, a1); acc_h4(v2, a2); acc_h4(v3, a3);
        acc_h4(v4, a0); acc_h4(v5, a1); acc_h4(v6, a2); acc_h4(v7, a3);
    }
    if (e + 4 <= m) {
        int4 ia = __ldg(&bp4[e >> 2]);
        uint2 v0 = __ldg(&F[(size_t)ia.x * 8 + lane]);
        uint2 v1 = __ldg(&F[(size_t)ia.y * 8 + lane]);
        uint2 v2 = __ldg(&F[(size_t)ia.z * 8 + lane]);
        uint2 v3 = __ldg(&F[(size_t)ia.w * 8 + lane]);
        acc_h4(v0, a0); acc_h4(v1, a1); acc_h4(v2, a2); acc_h4(v3, a3);
        e += 4;
    }
    const int* bp = (const int*)bp4;
    for (; e < m; e++) {
        int i0 = __ldg(&bp[e]);
        acc_h4(__ldg(&F[(size_t)i0 * 8 + lane]), a0);
    }
    if (deg > CAP) {   // exact overflow handling (normally empty)
        int oc = g_ovf_cnt;
        for (int i = 0; i < oc; i++) {
            if (g_ovf_dst[i] == node) {
                acc_h4(__ldg(&F[(size_t)g_ovf_src[i] * 8 + lane]), a0);
            }
        }
    }
    a0.x += a1.x + a2.x + a3.x;
    a0.y += a1.y + a2.y + a3.y;
    a0.z += a1.z + a2.z + a3.z;
    a0.w += a1.w + a2.w + a3.w;
    return a0;
}

// ---------------------------------------------------------------------------
// Gather layer 1: q = dinv*(dinv*sum + b1)  -> half store
// ---------------------------------------------------------------------------
__global__ void __launch_bounds__(256) k_gather1(const float* __restrict__ b1, int N) {
    int node = blockIdx.x * 32 + (threadIdx.x >> 3);
    int lane = threadIdx.x & 7;
    if (node >= N) return;

    float4 acc = gather_sum_h((const uint2*)g_ph, node, lane);

    float di = g_dinv[node];
    float4 b = ((const float4*)b1)[lane];
    __half2 q0 = __floats2half2_rn(di * (di * acc.x + b.x), di * (di * acc.y + b.y));
    __half2 q1 = __floats2half2_rn(di * (di * acc.z + b.z), di * (di * acc.w + b.w));
    uint2 st;
    st.x = *(unsigned*)&q0;
    st.y = *(unsigned*)&q1;
    ((uint2*)g_qh)[(size_t)node * 8 + lane] = st;
}

// ---------------------------------------------------------------------------
// Gather layer 2 + fused pooling (fp32 pool via red.v4)
// ---------------------------------------------------------------------------
__device__ __forceinline__ void red_add_v4(float* ptr, float4 v) {
    asm volatile("red.global.add.v4.f32 [%0], {%1, %2, %3, %4};"
                 :: "l"(ptr), "f"(v.x), "f"(v.y), "f"(v.z), "f"(v.w)
                 : "memory");
}

__global__ void __launch_bounds__(256) k_gather2(const void* __restrict__ batch, int N) {
    int node = blockIdx.x * 32 + (threadIdx.x >> 3);
    int lane = threadIdx.x & 7;
    if (node >= N) return;

    float4 acc = gather_sum_h((const uint2*)g_qh, node, lane);

    float di = g_dinv[node];
    float4 h = make_float4(di * acc.x, di * acc.y, di * acc.z, di * acc.w);
    int gidx = idx_get(batch, node, g_flags[1]);
    red_add_v4(g_pool + (size_t)gidx * C + lane * 4, h);
}

// ---------------------------------------------------------------------------
// Head phase A (grid = ceil(G/32) blocks x 128 thr; 4 threads per graph):
//   z[g] = relu((pool[g]/cnt)@W2 + b2)@fcW1 + fcb1), BN partial sums.
// ---------------------------------------------------------------------------
__global__ void k_headA(const void* __restrict__ batch, int N,
                        const float* __restrict__ W2, const float* __restrict__ b2,
                        const float* __restrict__ fcW1, const float* __restrict__ fcb1,
                        int G) {
    __shared__ float sW2[32 * 64];
    __shared__ float sF1[64 * 32];
    int tid = threadIdx.x;
    for (int i = tid; i < 2048; i += 128) { sW2[i] = W2[i]; sF1[i] = fcW1[i]; }
    __syncthreads();

    int gl = tid >> 2;
    int q = tid & 3;
    int g = blockIdx.x * 32 + gl;
    if (g >= G) return;
    int is64 = g_flags[1];

    int lo = 0, hi = N;
    while (lo < hi) { int m = (lo + hi) >> 1; if (idx_get(batch, m, is64) < g) lo = m + 1; else hi = m; }
    int start = lo;
    hi = N;
    while (lo < hi) { int m = (lo + hi) >> 1; if (idx_get(batch, m, is64) < g + 1) lo = m + 1; else hi = m; }
    int cnt = lo - start;
    float inv_cnt = 1.0f / (float)max(cnt, 1);

    float r[32];
#pragma unroll
    for (int i = 0; i < 32; i++) r[i] = __ldg(&g_pool[g * 32 + i]) * inv_cnt;

    float o2[16];
#pragma unroll
    for (int j = 0; j < 16; j++) o2[j] = __ldg(&b2[q * 16 + j]);
    for (int k = 0; k < 32; k++) {
        float rk = r[k];
        const float* wrow = sW2 + k * 64 + q * 16;
#pragma unroll
        for (int j = 0; j < 16; j++) o2[j] = fmaf(rk, wrow[j], o2[j]);
    }

    float zz[32];
#pragma unroll
    for (int i = 0; i < 32; i++) zz[i] = 0.0f;
    for (int j = 0; j < 16; j++) {
        float oj = o2[j];
        const float* frow = sF1 + (q * 16 + j) * 32;
#pragma unroll
        for (int i = 0; i < 32; i++) zz[i] = fmaf(oj, frow[i], zz[i]);
    }

    unsigned fm = 0xFFFFFFFFu;
#pragma unroll
    for (int i = 0; i < 32; i++) {
        zz[i] += __shfl_xor_sync(fm, zz[i], 1);
        zz[i] += __shfl_xor_sync(fm, zz[i], 2);
    }

    float z[32];
#pragma unroll
    for (int i = 0; i < 32; i++) z[i] = fmaxf(zz[i] + __ldg(&fcb1[i]), 0.0f);
    if (q == 0) {
#pragma unroll
        for (int i = 0; i < 32; i++) g_z[g * 32 + i] = z[i];
    }
    for (int i = 0; i < 32; i++) {
        float v = (q == 0) ? z[i] : 0.0f;
        float v2 = v * v;
#pragma unroll
        for (int o = 16; o > 0; o >>= 1) {
            v += __shfl_down_sync(fm, v, o);
            v2 += __shfl_down_sync(fm, v2, o);
        }
        if ((tid & 31) == 0) {
            atomicAdd(&g_bnsum[i], v);
            atomicAdd(&g_bnsq[i], v2);
        }
    }
}

// ---------------------------------------------------------------------------
// Head phase B (1 block, 1 thread/graph): batchnorm + fc2 + softplus
// ---------------------------------------------------------------------------
__global__ void k_headB(const float* __restrict__ gamma, const float* __restrict__ beta,
                        const float* __restrict__ fcW2, const float* __restrict__ fcb2,
                        float* __restrict__ out, int G) {
    __shared__ float smu[32], sis[32], sgam[32], sbet[32], sfw2[32];
    int tid = threadIdx.x;
    if (tid < 32) {
        float invG = 1.0f / (float)G;
        float mu = g_bnsum[tid] * invG;
        float var = g_bnsq[tid] * invG - mu * mu;
        smu[tid] = mu;
        sis[tid] = rsqrtf(var + 1e-5f);
        sgam[tid] = gamma[tid];
        sbet[tid] = beta[tid];
        sfw2[tid] = fcW2[tid];
    }
    __syncthreads();
    if (tid >= G) return;

    float acc = __ldg(&fcb2[0]);
#pragma unroll
    for (int i = 0; i < 32; i++) {
        float zb = (g_z[tid * 32 + i] - smu[i]) * sis[i] * sgam[i] + sbet[i];
        acc = fmaf(zb, sfw2[i], acc);
    }
    out[tid] = fmaxf(acc, 0.0f) + log1pf(expf(-fabsf(acc)));
}

// ---------------------------------------------------------------------------
extern "C" void kernel_launch(void* const* d_in, const int* in_sizes, int n_in,
                              void* d_out, int out_size) {
    const float* x     = (const float*)d_in[0];
    const void*  eidx  = d_in[1];
    const void*  batch = d_in[2];
    const float* W1    = (const float*)d_in[3];
    const float* b1    = (const float*)d_in[4];
    const float* W2    = (const float*)d_in[5];
    const float* b2    = (const float*)d_in[6];
    const float* fcW1  = (const float*)d_in[7];
    const float* fcb1  = (const float*)d_in[8];
    const float* gamma = (const float*)d_in[9];
    const float* beta  = (const float*)d_in[10];
    const float* fcW2  = (const float*)d_in[11];
    const float* fcb2  = (const float*)d_in[12];

    int N = in_sizes[0] / 128;
    int E = in_sizes[1] / 2;
    int G = out_size;

    void *pcur, *ppool;
    cudaGetSymbolAddress(&pcur, g_cur);
    cudaGetSymbolAddress(&ppool, g_pool);

    // Fork: branch B (s2) runs the GEMM, independent of the CSR build.
    cudaEventRecord(g_sp.ev_fork, 0);
    cudaStreamWaitEvent(g_sp.s2, g_sp.ev_fork, 0);
    k_gemm1<<<ceil_div(N, 256), 256, 0, g_sp.s2>>>(x, W1, N);
    cudaEventRecord(g_sp.ev_join, g_sp.s2);

    // Branch A: init + detect + place on the default stream.
    cudaMemsetAsync(pcur, 0, (size_t)N * sizeof(int));
    cudaMemsetAsync(ppool, 0, (size_t)G * C * sizeof(float));
    k_detect<<<1, 256>>>((const unsigned*)eidx, (long)2 * E,
                         (const unsigned*)batch, (long)N);
    k_place<<<ceil_div(E, 1024), 256>>>(eidx, E);

    // Join and finish serial tail.
    cudaStreamWaitEvent(0, g_sp.ev_join, 0);
    k_scale<<<ceil_div(N * 4, 256), 256>>>(N);
    k_gather1<<<ceil_div(N, 32), 256>>>(b1, N);
    k_gather2<<<ceil_div(N, 32), 256>>>(batch, N);
    k_headA<<<ceil_div(G, 32), 128>>>(batch, N, W2, b2, fcW1, fcb1, G);
    k_headB<<<1, G>>>(gamma, beta, fcW2, fcb2, (float*)d_out, G);
}

// round 15
// speedup vs baseline: 1.0593x; 1.0026x over previous
#include <cuda_runtime.h>
#include <cuda_fp16.h>
#include <cstdint>

// ---------------------------------------------------------------------------
// GCN via one-pass bucket-CSR gather, place || gemm via graph stream fork.
// Inter-layer features stored as fp16; fp32 accumulation. Gathers use
// 4 lanes/node (LDG.128 of 8 halves) with 32-bit address arithmetic.
//   branch A: memsets, detect, place (bucket[dst*64+slot]=src; cur==degree)
//   branch B: ph_raw = half(x @ W1)
//   join:     scale: dinv=rsqrt(1+deg); ph *= dinv (in place, half)
//   gather1:  q[n] = dinv*(dinv*(sum ph[nbr] + ph[n]) + b1)  -> qh (half)
//   gather2:  h[n] = dinv*(sum qh[nbr] + qh[n]); pool[batch[n]] += h (red.v4)
//   headA:    (8 blocks) z = relu((pool/cnt)@W2+b2)@fcW1+fcb1), BN partials
//   headB:    (1 block)  batchnorm + fc2 + softplus
// ---------------------------------------------------------------------------

#define MAXN 100000
#define MAXE 1600000
#define MAXG 256
#define C 32
#define CAP 64

__device__ int    g_bucket[MAXN * CAP];
__device__ int    g_cur[MAXN];         // placement cursor == degree afterwards
__device__ int    g_ovf_dst[MAXE];
__device__ int    g_ovf_src[MAXE];
__device__ int    g_ovf_cnt;
__device__ float  g_dinv[MAXN];
__device__ __half g_ph[MAXN * C];      // half p (raw then scaled in place)
__device__ __half g_qh[MAXN * C];      // half q, gather-2 source
__device__ float  g_pool[MAXG * C];
__device__ float  g_z[MAXG * 32];
__device__ float  g_bnsum[32];
__device__ float  g_bnsq[32];
__device__ int    g_flags[2];          // [0]=edge_index int64, [1]=batch int64

static inline int ceil_div(int a, int b) { return (a + b - 1) / b; }

// Host-side stream/event objects (created once; host objects, no device mem)
struct StreamPack {
    cudaStream_t s2;
    cudaEvent_t ev_fork, ev_join;
    StreamPack() {
        cudaStreamCreateWithFlags(&s2, cudaStreamNonBlocking);
        cudaEventCreateWithFlags(&ev_fork, cudaEventDisableTiming);
        cudaEventCreateWithFlags(&ev_join, cudaEventDisableTiming);
    }
};
static StreamPack g_sp;

__device__ __forceinline__ int idx_get(const void* p, long i, int is64) {
    // int64 path: load only the low 32-bit word (values are < 2^31)
    return is64 ? ((const int*)p)[2 * i] : ((const int*)p)[i];
}

// ---------------------------------------------------------------------------
// dtype detect + small scalar zero-inits
// ---------------------------------------------------------------------------
__global__ void k_detect(const unsigned* __restrict__ e, long ewords,
                         const unsigned* __restrict__ b, long bwords) {
    __shared__ unsigned se, sb;
    if (threadIdx.x == 0) { se = 0u; sb = 0u; g_ovf_cnt = 0; }
    if (threadIdx.x < 32) { g_bnsum[threadIdx.x] = 0.0f; g_bnsq[threadIdx.x] = 0.0f; }
    __syncthreads();
    unsigned a = 0u, c = 0u;
    long eh = ewords / 2, bh = bwords / 2;
    for (int s = 0; s < 16; s++) {
        long idx = (long)(threadIdx.x * 16 + s);
        long j = (idx * eh) / 4096;
        a |= e[2 * j + 1];
        long k = (idx * bh) / 4096;
        c |= b[2 * k + 1];
    }
    atomicOr(&se, a);
    atomicOr(&sb, c);
    __syncthreads();
    if (threadIdx.x == 0) {
        g_flags[0] = (se == 0u) ? 1 : 0;
        g_flags[1] = (sb == 0u) ? 1 : 0;
    }
}

// ---------------------------------------------------------------------------
// One-pass bucket placement, 4 independent edges/thread (batched), full grid.
// ---------------------------------------------------------------------------
__global__ void k_place(const void* __restrict__ eidx, int E) {
    int is64 = g_flags[0];
    int T = gridDim.x * blockDim.x;
    int tid = blockIdx.x * blockDim.x + threadIdx.x;

    int s[4], t[4], sl[4];
    bool v[4];
#pragma unroll
    for (int u = 0; u < 4; u++) {
        int e = tid + u * T;
        v[u] = e < E;
        if (v[u]) {
            s[u] = idx_get(eidx, e, is64);
            t[u] = idx_get(eidx, (long)E + e, is64);
        }
    }
#pragma unroll
    for (int u = 0; u < 4; u++) {
        if (v[u]) sl[u] = atomicAdd(&g_cur[t[u]], 1);
    }
#pragma unroll
    for (int u = 0; u < 4; u++) {
        if (v[u]) {
            if (sl[u] < CAP) g_bucket[(size_t)t[u] * CAP + sl[u]] = s[u];
            else { int o = atomicAdd(&g_ovf_cnt, 1); g_ovf_dst[o] = t[u]; g_ovf_src[o] = s[u]; }
        }
    }
}

// ---------------------------------------------------------------------------
// GEMM raw (packed fma.rn.f32x2): ph_raw[n,:] = half(x[n,:] @ W1)
// ---------------------------------------------------------------------------
__global__ void __launch_bounds__(256) k_gemm1(const float* __restrict__ x,
                                               const float* __restrict__ W1, int N) {
    __shared__ unsigned long long sW[128 * 16];
    const unsigned long long* Wp = (const unsigned long long*)W1;
    for (int i = threadIdx.x; i < 128 * 16; i += 256) sW[i] = Wp[i];
    __syncthreads();

    int n = blockIdx.x * 256 + threadIdx.x;
    if (n >= N) return;

    unsigned long long acc[16];
#pragma unroll
    for (int j = 0; j < 16; j++) acc[j] = 0ull;

    const float4* xr = (const float4*)(x + (size_t)n * 128);
#pragma unroll 2
    for (int k4 = 0; k4 < 32; k4++) {
        float4 xv = __ldg(&xr[k4]);
        const float* xf = (const float*)&xv;
#pragma unroll
        for (int kk = 0; kk < 4; kk++) {
            unsigned xb = __float_as_uint(xf[kk]);
            unsigned long long xx;
            asm("mov.b64 %0, {%1, %1};" : "=l"(xx) : "r"(xb));
            const unsigned long long* wr = sW + (k4 * 4 + kk) * 16;
#pragma unroll
            for (int j = 0; j < 16; j++) {
                asm("fma.rn.f32x2 %0, %1, %2, %0;"
                    : "+l"(acc[j]) : "l"(xx), "l"(wr[j]));
            }
        }
    }

    unsigned hh[16];
#pragma unroll
    for (int j = 0; j < 16; j++) {
        unsigned lo, hi;
        asm("mov.b64 {%0, %1}, %2;" : "=r"(lo), "=r"(hi) : "l"(acc[j]));
        __half2 h = __floats2half2_rn(__uint_as_float(lo), __uint_as_float(hi));
        hh[j] = *(unsigned*)&h;
    }
    uint4* out = (uint4*)(g_ph + (size_t)n * C);
#pragma unroll
    for (int j = 0; j < 4; j++) {
        out[j] = make_uint4(hh[4 * j], hh[4 * j + 1], hh[4 * j + 2], hh[4 * j + 3]);
    }
}

// ---------------------------------------------------------------------------
// scale (in-place half): dinv = rsqrt(1+deg); ph *= dinv
// one thread = one uint4 (8 halves); 4 threads per node row
// ---------------------------------------------------------------------------
__global__ void k_scale(int N) {
    int i = blockIdx.x * 256 + threadIdx.x;
    if (i >= N * 4) return;
    int n = i >> 2;
    float di = rsqrtf(1.0f + (float)g_cur[n]);
    if ((i & 3) == 0) g_dinv[n] = di;
    uint4 v = ((const uint4*)g_ph)[i];
    unsigned* w = (unsigned*)&v;
#pragma unroll
    for (int k = 0; k < 4; k++) {
        __half2 h = *(__half2*)&w[k];
        float2 f = __half22float2(h);
        __half2 r = __floats2half2_rn(f.x * di, f.y * di);
        w[k] = *(unsigned*)&r;
    }
    ((uint4*)g_ph)[i] = v;
}

// ---------------------------------------------------------------------------
// Gather core (half source): 4 threads/node, lane owns 8 halves (LDG.128).
// 32-bit address arithmetic; fp32 accumulation; 4-edge unroll, 2 acc banks.
// ---------------------------------------------------------------------------
__device__ __forceinline__ void acc_h8(uint4 v, float* a) {
    const unsigned* w = (const unsigned*)&v;
#pragma unroll
    for (int k = 0; k < 4; k++) {
        __half2 h = *(__half2*)&w[k];
        float2 f = __half22float2(h);
        a[2 * k]     += f.x;
        a[2 * k + 1] += f.y;
    }
}

__device__ __forceinline__ uint4 ldg_row(const char* base, unsigned row, unsigned laneoff) {
    return __ldg((const uint4*)(base + (row << 6) + laneoff));
}

__device__ __forceinline__ void gather_sum_h(const __half* __restrict__ Fsrc,
                                             int node, int lane, float* out) {
    int deg = g_cur[node];
    int m = deg < CAP ? deg : CAP;
    const int4* bp4 = (const int4*)(g_bucket + (size_t)node * CAP);
    const char* base = (const char*)Fsrc;
    unsigned laneoff = (unsigned)lane << 4;   // 16B per lane

    float a[8], b[8];
#pragma unroll
    for (int k = 0; k < 8; k++) { a[k] = 0.0f; b[k] = 0.0f; }
    acc_h8(ldg_row(base, (unsigned)node, laneoff), a);  // self-loop

    int e = 0;
    for (; e + 4 <= m; e += 4) {
        int4 ia = __ldg(&bp4[e >> 2]);
        uint4 v0 = ldg_row(base, (unsigned)ia.x, laneoff);
        uint4 v1 = ldg_row(base, (unsigned)ia.y, laneoff);
        uint4 v2 = ldg_row(base, (unsigned)ia.z, laneoff);
        uint4 v3 = ldg_row(base, (unsigned)ia.w, laneoff);
        acc_h8(v0, a); acc_h8(v1, b); acc_h8(v2, a); acc_h8(v3, b);
    }
    const int* bp = (const int*)bp4;
    for (; e < m; e++) {
        int i0 = __ldg(&bp[e]);
        acc_h8(ldg_row(base, (unsigned)i0, laneoff), a);
    }
    if (deg > CAP) {   // exact overflow handling (normally empty)
        int oc = g_ovf_cnt;
        for (int i = 0; i < oc; i++) {
            if (g_ovf_dst[i] == node) {
                acc_h8(ldg_row(base, (unsigned)g_ovf_src[i], laneoff), a);
            }
        }
    }
#pragma unroll
    for (int k = 0; k < 8; k++) out[k] = a[k] + b[k];
}

// ---------------------------------------------------------------------------
// Gather layer 1: q = dinv*(dinv*sum + b1)  -> half store (uint4)
// ---------------------------------------------------------------------------
__global__ void __launch_bounds__(256) k_gather1(const float* __restrict__ b1, int N) {
    int node = blockIdx.x * 64 + (threadIdx.x >> 2);
    int lane = threadIdx.x & 3;
    if (node >= N) return;

    float acc[8];
    gather_sum_h(g_ph, node, lane, acc);

    float di = g_dinv[node];
    float4 bv0 = ((const float4*)b1)[lane * 2];
    float4 bv1 = ((const float4*)b1)[lane * 2 + 1];
    const float* bb = (const float*)&bv0;  // bv0,bv1 contiguous? no — handle separately
    float q[8];
    q[0] = di * (di * acc[0] + bv0.x);
    q[1] = di * (di * acc[1] + bv0.y);
    q[2] = di * (di * acc[2] + bv0.z);
    q[3] = di * (di * acc[3] + bv0.w);
    q[4] = di * (di * acc[4] + bv1.x);
    q[5] = di * (di * acc[5] + bv1.y);
    q[6] = di * (di * acc[6] + bv1.z);
    q[7] = di * (di * acc[7] + bv1.w);
    (void)bb;

    unsigned hh[4];
#pragma unroll
    for (int k = 0; k < 4; k++) {
        __half2 h = __floats2half2_rn(q[2 * k], q[2 * k + 1]);
        hh[k] = *(unsigned*)&h;
    }
    ((uint4*)g_qh)[(size_t)node * 4 + lane] = make_uint4(hh[0], hh[1], hh[2], hh[3]);
}

// ---------------------------------------------------------------------------
// Gather layer 2 + fused pooling (fp32 pool via 2x red.v4 per lane)
// ---------------------------------------------------------------------------
__device__ __forceinline__ void red_add_v4(float* ptr, float4 v) {
    asm volatile("red.global.add.v4.f32 [%0], {%1, %2, %3, %4};"
                 :: "l"(ptr), "f"(v.x), "f"(v.y), "f"(v.z), "f"(v.w)
                 : "memory");
}

__global__ void __launch_bounds__(256) k_gather2(const void* __restrict__ batch, int N) {
    int node = blockIdx.x * 64 + (threadIdx.x >> 2);
    int lane = threadIdx.x & 3;
    if (node >= N) return;

    float acc[8];
    gather_sum_h(g_qh, node, lane, acc);

    float di = g_dinv[node];
    int gidx = idx_get(batch, node, g_flags[1]);
    float* pp = g_pool + (size_t)gidx * C + lane * 8;
    red_add_v4(pp,     make_float4(di * acc[0], di * acc[1], di * acc[2], di * acc[3]));
    red_add_v4(pp + 4, make_float4(di * acc[4], di * acc[5], di * acc[6], di * acc[7]));
}

// ---------------------------------------------------------------------------
// Head phase A (grid = ceil(G/32) blocks x 128 thr; 4 threads per graph):
//   z[g] = relu((pool[g]/cnt)@W2 + b2)@fcW1 + fcb1), BN partial sums.
// ---------------------------------------------------------------------------
__global__ void k_headA(const void* __restrict__ batch, int N,
                        const float* __restrict__ W2, const float* __restrict__ b2,
                        const float* __restrict__ fcW1, const float* __restrict__ fcb1,
                        int G) {
    __shared__ float sW2[32 * 64];
    __shared__ float sF1[64 * 32];
    int tid = threadIdx.x;
    for (int i = tid; i < 2048; i += 128) { sW2[i] = W2[i]; sF1[i] = fcW1[i]; }
    __syncthreads();

    int gl = tid >> 2;
    int q = tid & 3;
    int g = blockIdx.x * 32 + gl;
    if (g >= G) return;
    int is64 = g_flags[1];

    int lo = 0, hi = N;
    while (lo < hi) { int m = (lo + hi) >> 1; if (idx_get(batch, m, is64) < g) lo = m + 1; else hi = m; }
    int start = lo;
    hi = N;
    while (lo < hi) { int m = (lo + hi) >> 1; if (idx_get(batch, m, is64) < g + 1) lo = m + 1; else hi = m; }
    int cnt = lo - start;
    float inv_cnt = 1.0f / (float)max(cnt, 1);

    float r[32];
#pragma unroll
    for (int i = 0; i < 32; i++) r[i] = __ldg(&g_pool[g * 32 + i]) * inv_cnt;

    float o2[16];
#pragma unroll
    for (int j = 0; j < 16; j++) o2[j] = __ldg(&b2[q * 16 + j]);
    for (int k = 0; k < 32; k++) {
        float rk = r[k];
        const float* wrow = sW2 + k * 64 + q * 16;
#pragma unroll
        for (int j = 0; j < 16; j++) o2[j] = fmaf(rk, wrow[j], o2[j]);
    }

    float zz[32];
#pragma unroll
    for (int i = 0; i < 32; i++) zz[i] = 0.0f;
    for (int j = 0; j < 16; j++) {
        float oj = o2[j];
        const float* frow = sF1 + (q * 16 + j) * 32;
#pragma unroll
        for (int i = 0; i < 32; i++) zz[i] = fmaf(oj, frow[i], zz[i]);
    }

    unsigned fm = 0xFFFFFFFFu;
#pragma unroll
    for (int i = 0; i < 32; i++) {
        zz[i] += __shfl_xor_sync(fm, zz[i], 1);
        zz[i] += __shfl_xor_sync(fm, zz[i], 2);
    }

    float z[32];
#pragma unroll
    for (int i = 0; i < 32; i++) z[i] = fmaxf(zz[i] + __ldg(&fcb1[i]), 0.0f);
    if (q == 0) {
#pragma unroll
        for (int i = 0; i < 32; i++) g_z[g * 32 + i] = z[i];
    }
    for (int i = 0; i < 32; i++) {
        float v = (q == 0) ? z[i] : 0.0f;
        float v2 = v * v;
#pragma unroll
        for (int o = 16; o > 0; o >>= 1) {
            v += __shfl_down_sync(fm, v, o);
            v2 += __shfl_down_sync(fm, v2, o);
        }
        if ((tid & 31) == 0) {
            atomicAdd(&g_bnsum[i], v);
            atomicAdd(&g_bnsq[i], v2);
        }
    }
}

// ---------------------------------------------------------------------------
// Head phase B (1 block, 1 thread/graph): batchnorm + fc2 + softplus
// ---------------------------------------------------------------------------
__global__ void k_headB(const float* __restrict__ gamma, const float* __restrict__ beta,
                        const float* __restrict__ fcW2, const float* __restrict__ fcb2,
                        float* __restrict__ out, int G) {
    __shared__ float smu[32], sis[32], sgam[32], sbet[32], sfw2[32];
    int tid = threadIdx.x;
    if (tid < 32) {
        float invG = 1.0f / (float)G;
        float mu = g_bnsum[tid] * invG;
        float var = g_bnsq[tid] * invG - mu * mu;
        smu[tid] = mu;
        sis[tid] = rsqrtf(var + 1e-5f);
        sgam[tid] = gamma[tid];
        sbet[tid] = beta[tid];
        sfw2[tid] = fcW2[tid];
    }
    __syncthreads();
    if (tid >= G) return;

    float acc = __ldg(&fcb2[0]);
#pragma unroll
    for (int i = 0; i < 32; i++) {
        float zb = (g_z[tid * 32 + i] - smu[i]) * sis[i] * sgam[i] + sbet[i];
        acc = fmaf(zb, sfw2[i], acc);
    }
    out[tid] = fmaxf(acc, 0.0f) + log1pf(expf(-fabsf(acc)));
}

// ---------------------------------------------------------------------------
extern "C" void kernel_launch(void* const* d_in, const int* in_sizes, int n_in,
                              void* d_out, int out_size) {
    const float* x     = (const float*)d_in[0];
    const void*  eidx  = d_in[1];
    const void*  batch = d_in[2];
    const float* W1    = (const float*)d_in[3];
    const float* b1    = (const float*)d_in[4];
    const float* W2    = (const float*)d_in[5];
    const float* b2    = (const float*)d_in[6];
    const float* fcW1  = (const float*)d_in[7];
    const float* fcb1  = (const float*)d_in[8];
    const float* gamma = (const float*)d_in[9];
    const float* beta  = (const float*)d_in[10];
    const float* fcW2  = (const float*)d_in[11];
    const float* fcb2  = (const float*)d_in[12];

    int N = in_sizes[0] / 128;
    int E = in_sizes[1] / 2;
    int G = out_size;

    void *pcur, *ppool;
    cudaGetSymbolAddress(&pcur, g_cur);
    cudaGetSymbolAddress(&ppool, g_pool);

    // Fork: branch B (s2) runs the GEMM, independent of the CSR build.
    cudaEventRecord(g_sp.ev_fork, 0);
    cudaStreamWaitEvent(g_sp.s2, g_sp.ev_fork, 0);
    k_gemm1<<<ceil_div(N, 256), 256, 0, g_sp.s2>>>(x, W1, N);
    cudaEventRecord(g_sp.ev_join, g_sp.s2);

    // Branch A: init + detect + place on the default stream.
    cudaMemsetAsync(pcur, 0, (size_t)N * sizeof(int));
    cudaMemsetAsync(ppool, 0, (size_t)G * C * sizeof(float));
    k_detect<<<1, 256>>>((const unsigned*)eidx, (long)2 * E,
                         (const unsigned*)batch, (long)N);
    k_place<<<ceil_div(E, 1024), 256>>>(eidx, E);

    // Join and finish serial tail.
    cudaStreamWaitEvent(0, g_sp.ev_join, 0);
    k_scale<<<ceil_div(N * 4, 256), 256>>>(N);
    k_gather1<<<ceil_div(N, 64), 256>>>(b1, N);
    k_gather2<<<ceil_div(N, 64), 256>>>(batch, N);
    k_headA<<<ceil_div(G, 32), 128>>>(batch, N, W2, b2, fcW1, fcb1, G);
    k_headB<<<1, G>>>(gamma, beta, fcW2, fcb2, (float*)d_out, G);
}

// round 16
// speedup vs baseline: 1.1016x; 1.0399x over previous
#include <cuda_runtime.h>
#include <cuda_fp16.h>
#include <cstdint>

// ---------------------------------------------------------------------------
// GCN, fp16 inter-layer features, fused persistent middle kernel:
//   branch A: memsets, place (bucket[dst*64+slot]=src; cur==degree; inline
//             edge-dtype detect per block)
//   branch B: ph_raw = half(x @ W1)
//   k_mid (persistent, 592 blocks co-resident):
//     phase0: dinv=rsqrt(1+deg); ph *= dinv        | global barrier
//     phase1: qh[n] = half(dn*(dn*(sum ph)+b1))    | global barrier
//     phase2: h[n] = dn*sum qh; pool[batch[n]] += h (red.v4)
//   headA: (8 blocks) z = relu((pool/cnt)@W2+b2)@fcW1+fcb1), BN partials
//   headB: (1 block)  batchnorm + fc2 + softplus
// ---------------------------------------------------------------------------

#define MAXN 100000
#define MAXE 1600000
#define MAXG 256
#define C 32
#define CAP 64
#define MIDGRID 592

__device__ int    g_bucket[MAXN * CAP];
__device__ int    g_cur[MAXN];         // placement cursor == degree afterwards
__device__ int    g_ovf_dst[MAXE];
__device__ int    g_ovf_src[MAXE];
__device__ int    g_ovf_cnt;
__device__ float  g_dinv[MAXN];
__device__ __half g_ph[MAXN * C];      // half p (raw, then scaled in place)
__device__ __half g_qh[MAXN * C];      // half q
__device__ float  g_pool[MAXG * C];
__device__ float  g_z[MAXG * 32];
__device__ float  g_bn[64];            // [0:32) sum, [32:64) sumsq
__device__ int    g_sync[2];           // barrier counters

static inline int ceil_div(int a, int b) { return (a + b - 1) / b; }

// Host-side stream/event objects (created once; host objects, no device mem)
struct StreamPack {
    cudaStream_t s2;
    cudaEvent_t ev_fork, ev_join;
    StreamPack() {
        cudaStreamCreateWithFlags(&s2, cudaStreamNonBlocking);
        cudaEventCreateWithFlags(&ev_fork, cudaEventDisableTiming);
        cudaEventCreateWithFlags(&ev_join, cudaEventDisableTiming);
    }
};
static StreamPack g_sp;

__device__ __forceinline__ int idx_get(const void* p, long i, int is64) {
    // int64 path: load only the low 32-bit word (values are < 2^31)
    return is64 ? ((const int*)p)[2 * i] : ((const int*)p)[i];
}

// Per-block dtype detection: for little-endian non-negative int64, every odd
// 32-bit word is 0. Sample 256 odd words spread over the first half of the
// buffer (safe for both widths). Warp 0 only; result in *flag after syncthreads.
__device__ __forceinline__ void detect_dtype(const unsigned* buf, long nelem_min,
                                             int* flag /*smem*/) {
    if (threadIdx.x < 32) {
        unsigned a = 0u;
        long half = nelem_min / 2;
        for (int s = 0; s < 8; s++) {
            long idx = (long)(threadIdx.x * 8 + s);
            long j = (idx * half) / 256;       // j in [0, half)
            a |= buf[2 * j + 1];
        }
#pragma unroll
        for (int o = 16; o > 0; o >>= 1) a |= __shfl_down_sync(0xFFFFFFFFu, a, o);
        if (threadIdx.x == 0) *flag = (a == 0u) ? 1 : 0;
    }
    __syncthreads();
}

// ---------------------------------------------------------------------------
// One-pass bucket placement, 4 independent edges/thread; inline edge-dtype
// detect per block; block 0 also zeroes g_bn/g_sync (tiny, used later).
// ---------------------------------------------------------------------------
__global__ void k_place(const void* __restrict__ eidx, int E) {
    __shared__ int s_is64;
    detect_dtype((const unsigned*)eidx, (long)2 * E, &s_is64);
    int is64 = s_is64;

    if (blockIdx.x == 0) {
        if (threadIdx.x < 64) g_bn[threadIdx.x] = 0.0f;
        if (threadIdx.x >= 64 && threadIdx.x < 66) g_sync[threadIdx.x - 64] = 0;
    }

    int T = gridDim.x * blockDim.x;
    int tid = blockIdx.x * blockDim.x + threadIdx.x;

    int s[4], t[4], sl[4];
    bool v[4];
#pragma unroll
    for (int u = 0; u < 4; u++) {
        int e = tid + u * T;
        v[u] = e < E;
        if (v[u]) {
            s[u] = idx_get(eidx, e, is64);
            t[u] = idx_get(eidx, (long)E + e, is64);
        }
    }
#pragma unroll
    for (int u = 0; u < 4; u++) {
        if (v[u]) sl[u] = atomicAdd(&g_cur[t[u]], 1);
    }
#pragma unroll
    for (int u = 0; u < 4; u++) {
        if (v[u]) {
            if (sl[u] < CAP) g_bucket[(size_t)t[u] * CAP + sl[u]] = s[u];
            else { int o = atomicAdd(&g_ovf_cnt, 1); g_ovf_dst[o] = t[u]; g_ovf_src[o] = s[u]; }
        }
    }
}

// ---------------------------------------------------------------------------
// GEMM raw (packed fma.rn.f32x2): ph_raw[n,:] = half(x[n,:] @ W1)
// ---------------------------------------------------------------------------
__global__ void __launch_bounds__(256) k_gemm1(const float* __restrict__ x,
                                               const float* __restrict__ W1, int N) {
    __shared__ unsigned long long sW[128 * 16];
    const unsigned long long* Wp = (const unsigned long long*)W1;
    for (int i = threadIdx.x; i < 128 * 16; i += 256) sW[i] = Wp[i];
    __syncthreads();

    int n = blockIdx.x * 256 + threadIdx.x;
    if (n >= N) return;

    unsigned long long acc[16];
#pragma unroll
    for (int j = 0; j < 16; j++) acc[j] = 0ull;

    const float4* xr = (const float4*)(x + (size_t)n * 128);
#pragma unroll 2
    for (int k4 = 0; k4 < 32; k4++) {
        float4 xv = __ldg(&xr[k4]);
        const float* xf = (const float*)&xv;
#pragma unroll
        for (int kk = 0; kk < 4; kk++) {
            unsigned xb = __float_as_uint(xf[kk]);
            unsigned long long xx;
            asm("mov.b64 %0, {%1, %1};" : "=l"(xx) : "r"(xb));
            const unsigned long long* wr = sW + (k4 * 4 + kk) * 16;
#pragma unroll
            for (int j = 0; j < 16; j++) {
                asm("fma.rn.f32x2 %0, %1, %2, %0;"
                    : "+l"(acc[j]) : "l"(xx), "l"(wr[j]));
            }
        }
    }

    unsigned hh[16];
#pragma unroll
    for (int j = 0; j < 16; j++) {
        unsigned lo, hi;
        asm("mov.b64 {%0, %1}, %2;" : "=r"(lo), "=r"(hi) : "l"(acc[j]));
        __half2 h = __floats2half2_rn(__uint_as_float(lo), __uint_as_float(hi));
        hh[j] = *(unsigned*)&h;
    }
    uint4* out = (uint4*)(g_ph + (size_t)n * C);
#pragma unroll
    for (int j = 0; j < 4; j++) {
        out[j] = make_uint4(hh[4 * j], hh[4 * j + 1], hh[4 * j + 2], hh[4 * j + 3]);
    }
}

// ---------------------------------------------------------------------------
// Gather helpers (half source): 4 threads/node, lane owns 8 halves (LDG.128),
// 32-bit address arithmetic, fp32 accumulation.
// ---------------------------------------------------------------------------
__device__ __forceinline__ void acc_h8(uint4 v, float* a) {
    const unsigned* w = (const unsigned*)&v;
#pragma unroll
    for (int k = 0; k < 4; k++) {
        __half2 h = *(__half2*)&w[k];
        float2 f = __half22float2(h);
        a[2 * k]     += f.x;
        a[2 * k + 1] += f.y;
    }
}

__device__ __forceinline__ uint4 ldg_row(const char* base, unsigned row, unsigned laneoff) {
    return __ldg((const uint4*)(base + (row << 6) + laneoff));
}

__device__ __forceinline__ void gather_sum_h(const __half* __restrict__ Fsrc,
                                             int node, int lane, float* out) {
    int deg = g_cur[node];
    int m = deg < CAP ? deg : CAP;
    const int4* bp4 = (const int4*)(g_bucket + (size_t)node * CAP);
    const char* base = (const char*)Fsrc;
    unsigned laneoff = (unsigned)lane << 4;

    float a[8], b[8];
#pragma unroll
    for (int k = 0; k < 8; k++) { a[k] = 0.0f; b[k] = 0.0f; }
    acc_h8(ldg_row(base, (unsigned)node, laneoff), a);  // self-loop

    int e = 0;
    for (; e + 4 <= m; e += 4) {
        int4 ia = __ldg(&bp4[e >> 2]);
        uint4 v0 = ldg_row(base, (unsigned)ia.x, laneoff);
        uint4 v1 = ldg_row(base, (unsigned)ia.y, laneoff);
        uint4 v2 = ldg_row(base, (unsigned)ia.z, laneoff);
        uint4 v3 = ldg_row(base, (unsigned)ia.w, laneoff);
        acc_h8(v0, a); acc_h8(v1, b); acc_h8(v2, a); acc_h8(v3, b);
    }
    const int* bp = (const int*)bp4;
    for (; e < m; e++) {
        int i0 = __ldg(&bp[e]);
        acc_h8(ldg_row(base, (unsigned)i0, laneoff), a);
    }
    if (deg > CAP) {   // exact overflow handling (normally empty)
        int oc = g_ovf_cnt;
        for (int i = 0; i < oc; i++) {
            if (g_ovf_dst[i] == node) {
                acc_h8(ldg_row(base, (unsigned)g_ovf_src[i], laneoff), a);
            }
        }
    }
#pragma unroll
    for (int k = 0; k < 8; k++) out[k] = a[k] + b[k];
}

// Global barrier: all gridDim.x blocks co-resident (guaranteed by launch
// bounds + grid size). Publish via threadfence+counter, spin, fence, sync.
__device__ __forceinline__ void gbar(int* ctr, int target) {
    __syncthreads();
    if (threadIdx.x == 0) {
        __threadfence();
        atomicAdd(ctr, 1);
        while (*(volatile int*)ctr < target) { }
        __threadfence();
    }
    __syncthreads();
}

// ---------------------------------------------------------------------------
// Persistent middle kernel: scale | bar | gather1 | bar | gather2+pool
// ---------------------------------------------------------------------------
__global__ void __launch_bounds__(256, 4) k_mid(const float* __restrict__ b1,
                                                const void* __restrict__ batch,
                                                int N) {
    __shared__ int s_is64b;
    detect_dtype((const unsigned*)batch, (long)N, &s_is64b);
    int is64b = s_is64b;

    int grid = gridDim.x;
    int chunk = (N + grid - 1) / grid;
    int n0 = blockIdx.x * chunk;
    int n1 = n0 + chunk; if (n1 > N) n1 = N;
    if (n0 > N) n0 = N;

    // ---- phase 0: dinv + in-place scale of ph ----
    for (int i = n0 * 4 + (int)threadIdx.x; i < n1 * 4; i += 256) {
        int n = i >> 2;
        float di = rsqrtf(1.0f + (float)g_cur[n]);
        if ((i & 3) == 0) g_dinv[n] = di;
        uint4 v = ((const uint4*)g_ph)[i];
        unsigned* w = (unsigned*)&v;
#pragma unroll
        for (int k = 0; k < 4; k++) {
            __half2 h = *(__half2*)&w[k];
            float2 f = __half22float2(h);
            __half2 r = __floats2half2_rn(f.x * di, f.y * di);
            w[k] = *(unsigned*)&r;
        }
        ((uint4*)g_ph)[i] = v;
    }

    gbar(&g_sync[0], grid);

    // ---- phase 1: gather1, q = dinv*(dinv*sum + b1) -> half ----
    {
        int lane = threadIdx.x & 3;
        float4 bv0 = ((const float4*)b1)[lane * 2];
        float4 bv1 = ((const float4*)b1)[lane * 2 + 1];
        for (int base = n0; base < n1; base += 64) {
            int node = base + ((int)threadIdx.x >> 2);
            if (node < n1) {
                float acc[8];
                gather_sum_h(g_ph, node, lane, acc);
                float di = g_dinv[node];
                float q[8];
                q[0] = di * (di * acc[0] + bv0.x);
                q[1] = di * (di * acc[1] + bv0.y);
                q[2] = di * (di * acc[2] + bv0.z);
                q[3] = di * (di * acc[3] + bv0.w);
                q[4] = di * (di * acc[4] + bv1.x);
                q[5] = di * (di * acc[5] + bv1.y);
                q[6] = di * (di * acc[6] + bv1.z);
                q[7] = di * (di * acc[7] + bv1.w);
                unsigned hh[4];
#pragma unroll
                for (int k = 0; k < 4; k++) {
                    __half2 h = __floats2half2_rn(q[2 * k], q[2 * k + 1]);
                    hh[k] = *(unsigned*)&h;
                }
                ((uint4*)g_qh)[(size_t)node * 4 + lane] =
                    make_uint4(hh[0], hh[1], hh[2], hh[3]);
            }
        }
    }

    gbar(&g_sync[1], grid);

    // ---- phase 2: gather2 + fused pooling ----
    {
        int lane = threadIdx.x & 3;
        for (int base = n0; base < n1; base += 64) {
            int node = base + ((int)threadIdx.x >> 2);
            if (node < n1) {
                float acc[8];
                gather_sum_h(g_qh, node, lane, acc);
                float di = g_dinv[node];
                int gidx = idx_get(batch, node, is64b);
                float* pp = g_pool + (size_t)gidx * C + lane * 8;
                float4 h0 = make_float4(di * acc[0], di * acc[1], di * acc[2], di * acc[3]);
                float4 h1 = make_float4(di * acc[4], di * acc[5], di * acc[6], di * acc[7]);
                asm volatile("red.global.add.v4.f32 [%0], {%1, %2, %3, %4};"
                             :: "l"(pp), "f"(h0.x), "f"(h0.y), "f"(h0.z), "f"(h0.w) : "memory");
                asm volatile("red.global.add.v4.f32 [%0], {%1, %2, %3, %4};"
                             :: "l"(pp + 4), "f"(h1.x), "f"(h1.y), "f"(h1.z), "f"(h1.w) : "memory");
            }
        }
    }
}

// ---------------------------------------------------------------------------
// Head phase A (8 blocks x 128 thr; 4 threads per graph): z + BN partials
// ---------------------------------------------------------------------------
__global__ void k_headA(const void* __restrict__ batch, int N,
                        const float* __restrict__ W2, const float* __restrict__ b2,
                        const float* __restrict__ fcW1, const float* __restrict__ fcb1,
                        int G) {
    __shared__ float sW2[32 * 64];
    __shared__ float sF1[64 * 32];
    __shared__ int s_is64b;
    detect_dtype((const unsigned*)batch, (long)N, &s_is64b);
    int is64 = s_is64b;

    int tid = threadIdx.x;
    for (int i = tid; i < 2048; i += 128) { sW2[i] = W2[i]; sF1[i] = fcW1[i]; }
    __syncthreads();

    int gl = tid >> 2;
    int q = tid & 3;
    int g = blockIdx.x * 32 + gl;
    if (g >= G) return;

    int lo = 0, hi = N;
    while (lo < hi) { int m = (lo + hi) >> 1; if (idx_get(batch, m, is64) < g) lo = m + 1; else hi = m; }
    int start = lo;
    hi = N;
    while (lo < hi) { int m = (lo + hi) >> 1; if (idx_get(batch, m, is64) < g + 1) lo = m + 1; else hi = m; }
    int cnt = lo - start;
    float inv_cnt = 1.0f / (float)max(cnt, 1);

    float r[32];
#pragma unroll
    for (int i = 0; i < 32; i++) r[i] = __ldg(&g_pool[g * 32 + i]) * inv_cnt;

    float o2[16];
#pragma unroll
    for (int j = 0; j < 16; j++) o2[j] = __ldg(&b2[q * 16 + j]);
    for (int k = 0; k < 32; k++) {
        float rk = r[k];
        const float* wrow = sW2 + k * 64 + q * 16;
#pragma unroll
        for (int j = 0; j < 16; j++) o2[j] = fmaf(rk, wrow[j], o2[j]);
    }

    float zz[32];
#pragma unroll
    for (int i = 0; i < 32; i++) zz[i] = 0.0f;
    for (int j = 0; j < 16; j++) {
        float oj = o2[j];
        const float* frow = sF1 + (q * 16 + j) * 32;
#pragma unroll
        for (int i = 0; i < 32; i++) zz[i] = fmaf(oj, frow[i], zz[i]);
    }

    unsigned fm = 0xFFFFFFFFu;
#pragma unroll
    for (int i = 0; i < 32; i++) {
        zz[i] += __shfl_xor_sync(fm, zz[i], 1);
        zz[i] += __shfl_xor_sync(fm, zz[i], 2);
    }

    float z[32];
#pragma unroll
    for (int i = 0; i < 32; i++) z[i] = fmaxf(zz[i] + __ldg(&fcb1[i]), 0.0f);
    if (q == 0) {
#pragma unroll
        for (int i = 0; i < 32; i++) g_z[g * 32 + i] = z[i];
    }
    for (int i = 0; i < 32; i++) {
        float v = (q == 0) ? z[i] : 0.0f;
        float v2 = v * v;
#pragma unroll
        for (int o = 16; o > 0; o >>= 1) {
            v += __shfl_down_sync(fm, v, o);
            v2 += __shfl_down_sync(fm, v2, o);
        }
        if ((tid & 31) == 0) {
            atomicAdd(&g_bn[i], v);
            atomicAdd(&g_bn[32 + i], v2);
        }
    }
}

// ---------------------------------------------------------------------------
// Head phase B (1 block, 1 thread/graph): batchnorm + fc2 + softplus
// ---------------------------------------------------------------------------
__global__ void k_headB(const float* __restrict__ gamma, const float* __restrict__ beta,
                        const float* __restrict__ fcW2, const float* __restrict__ fcb2,
                        float* __restrict__ out, int G) {
    __shared__ float smu[32], sis[32], sgam[32], sbet[32], sfw2[32];
    int tid = threadIdx.x;
    if (tid < 32) {
        float invG = 1.0f / (float)G;
        float mu = g_bn[tid] * invG;
        float var = g_bn[32 + tid] * invG - mu * mu;
        smu[tid] = mu;
        sis[tid] = rsqrtf(var + 1e-5f);
        sgam[tid] = gamma[tid];
        sbet[tid] = beta[tid];
        sfw2[tid] = fcW2[tid];
    }
    __syncthreads();
    if (tid >= G) return;

    float acc = __ldg(&fcb2[0]);
#pragma unroll
    for (int i = 0; i < 32; i++) {
        float zb = (g_z[tid * 32 + i] - smu[i]) * sis[i] * sgam[i] + sbet[i];
        acc = fmaf(zb, sfw2[i], acc);
    }
    out[tid] = fmaxf(acc, 0.0f) + log1pf(expf(-fabsf(acc)));
}

// ---------------------------------------------------------------------------
extern "C" void kernel_launch(void* const* d_in, const int* in_sizes, int n_in,
                              void* d_out, int out_size) {
    const float* x     = (const float*)d_in[0];
    const void*  eidx  = d_in[1];
    const void*  batch = d_in[2];
    const float* W1    = (const float*)d_in[3];
    const float* b1    = (const float*)d_in[4];
    const float* W2    = (const float*)d_in[5];
    const float* b2    = (const float*)d_in[6];
    const float* fcW1  = (const float*)d_in[7];
    const float* fcb1  = (const float*)d_in[8];
    const float* gamma = (const float*)d_in[9];
    const float* beta  = (const float*)d_in[10];
    const float* fcW2  = (const float*)d_in[11];
    const float* fcb2  = (const float*)d_in[12];

    int N = in_sizes[0] / 128;
    int E = in_sizes[1] / 2;
    int G = out_size;

    void *pcur, *ppool, *povf;
    cudaGetSymbolAddress(&pcur, g_cur);
    cudaGetSymbolAddress(&ppool, g_pool);
    cudaGetSymbolAddress(&povf, g_ovf_cnt);

    // Fork: branch B (s2) runs the GEMM, independent of the CSR build.
    cudaEventRecord(g_sp.ev_fork, 0);
    cudaStreamWaitEvent(g_sp.s2, g_sp.ev_fork, 0);
    k_gemm1<<<ceil_div(N, 256), 256, 0, g_sp.s2>>>(x, W1, N);
    cudaEventRecord(g_sp.ev_join, g_sp.s2);

    // Branch A: init + place on the default stream.
    cudaMemsetAsync(pcur, 0, (size_t)N * sizeof(int));
    cudaMemsetAsync(ppool, 0, (size_t)G * C * sizeof(float));
    cudaMemsetAsync(povf, 0, sizeof(int));
    k_place<<<ceil_div(E, 1024), 256>>>(eidx, E);

    // Join and run the fused persistent tail.
    cudaStreamWaitEvent(0, g_sp.ev_join, 0);
    k_mid<<<MIDGRID, 256>>>(b1, batch, N);
    k_headA<<<ceil_div(G, 32), 128>>>(batch, N, W2, b2, fcW1, fcb1, G);
    k_headB<<<1, G>>>(gamma, beta, fcW2, fcb2, (float*)d_out, G);
}